// round 9
// baseline (speedup 1.0000x reference)
#include <cuda_runtime.h>
#include <cuda_fp16.h>
#include <math.h>
#include <stdint.h>

#define BATCH 8
#define SEQ   512
#define HDIM  1024
#define FFDIM 4096
#define NHEAD 16
#define DHEAD 64
#define MROWS (BATCH*SEQ)   // 4096

// ---------------------------------------------------------------------------
// Static device scratch
// ---------------------------------------------------------------------------
__device__ float g_t1[(size_t)MROWS * HDIM];
__device__ float g_attn[(size_t)MROWS * HDIM];

__device__ __half g_xh[(size_t)MROWS * HDIM];
__device__ __half g_qh[(size_t)MROWS * HDIM];       // Q (prescaled 0.125)
__device__ __half g_kh[(size_t)MROWS * HDIM];
__device__ __half g_vh[(size_t)MROWS * HDIM];
__device__ __half g_ctx[(size_t)MROWS * HDIM];
__device__ __half g_attnh[(size_t)MROWS * HDIM];
__device__ __half g_inter[(size_t)MROWS * FFDIM];
__device__ __half g_adder[(size_t)BATCH * SEQ * SEQ];

__device__ __half g_wqkv[(size_t)3 * HDIM * HDIM];  // packed, transposed [N,K]
__device__ __half g_wao[(size_t)HDIM * HDIM];
__device__ __half g_wi[(size_t)FFDIM * HDIM];
__device__ __half g_wo[(size_t)HDIM * FFDIM];

__device__ __forceinline__ float gelu_tanh(float x) {
    float x3 = x * x * x;
    return 0.5f * x * (1.0f + tanhf(0.7978845608028654f * (x + 0.044715f * x3)));
}
__device__ __forceinline__ uint32_t h2_as_u32(__half2 h) {
    union { __half2 h2; uint32_t u; } c; c.h2 = h; return c.u;
}

// ---------------------------------------------------------------------------
// PTX helpers
// ---------------------------------------------------------------------------
__device__ __forceinline__ uint32_t smem_u32(const void* p) {
    uint32_t a;
    asm("{ .reg .u64 t; cvta.to.shared.u64 t, %1; cvt.u32.u64 %0, t; }"
        : "=r"(a) : "l"(p));
    return a;
}
__device__ __forceinline__ void cp16(uint32_t saddr, const void* gaddr) {
    asm volatile("cp.async.cg.shared.global [%0], [%1], 16;" :: "r"(saddr), "l"(gaddr));
}
#define CP_COMMIT() asm volatile("cp.async.commit_group;" ::: "memory")
#define CP_WAIT(n)  asm volatile("cp.async.wait_group %0;" :: "n"(n) : "memory")

__device__ __forceinline__ void ldm_x4(uint32_t* r, uint32_t addr) {
    asm volatile("ldmatrix.sync.aligned.m8n8.x4.shared.b16 {%0,%1,%2,%3}, [%4];"
        : "=r"(r[0]), "=r"(r[1]), "=r"(r[2]), "=r"(r[3]) : "r"(addr));
}
__device__ __forceinline__ void ldm_x4_t(uint32_t* r, uint32_t addr) {
    asm volatile("ldmatrix.sync.aligned.m8n8.x4.trans.shared.b16 {%0,%1,%2,%3}, [%4];"
        : "=r"(r[0]), "=r"(r[1]), "=r"(r[2]), "=r"(r[3]) : "r"(addr));
}
__device__ __forceinline__ void mma_f16(float* c, const uint32_t* a, const uint32_t* b) {
    asm volatile(
        "mma.sync.aligned.m16n8k16.row.col.f32.f16.f16.f32 "
        "{%0,%1,%2,%3}, {%4,%5,%6,%7}, {%8,%9}, {%0,%1,%2,%3};"
        : "+f"(c[0]), "+f"(c[1]), "+f"(c[2]), "+f"(c[3])
        : "r"(a[0]), "r"(a[1]), "r"(a[2]), "r"(a[3]), "r"(b[0]), "r"(b[1]));
}

// ---------------------------------------------------------------------------
// Elementwise fp32 -> fp16
// ---------------------------------------------------------------------------
__global__ __launch_bounds__(256)
void cvt_kernel(const float* __restrict__ x, __half* __restrict__ h, int n4)
{
    int i = blockIdx.x * blockDim.x + threadIdx.x;
    if (i >= n4) return;
    float4 v = ((const float4*)x)[i];
    union { __half2 h2[2]; uint2 u; } p;
    p.h2[0] = __floats2half2_rn(v.x, v.y);
    p.h2[1] = __floats2half2_rn(v.z, v.w);
    ((uint2*)h)[i] = p.u;
}

__global__ __launch_bounds__(256)
void mask_cvt_kernel(const int* __restrict__ m, __half* __restrict__ a, int n4)
{
    int i = blockIdx.x * blockDim.x + threadIdx.x;
    if (i >= n4) return;
    int4 v = ((const int4*)m)[i];
    union { __half2 h2[2]; uint2 u; } p;
    p.h2[0] = __floats2half2_rn((1.0f - (float)v.x) * -10000.0f,
                                (1.0f - (float)v.y) * -10000.0f);
    p.h2[1] = __floats2half2_rn((1.0f - (float)v.z) * -10000.0f,
                                (1.0f - (float)v.w) * -10000.0f);
    ((uint2*)a)[i] = p.u;
}

// ---------------------------------------------------------------------------
// W[K,N] fp32 -> T[N,K] fp16. Tile 64(k) x 32(n); __half2 coalesced writes.
// grid: (N/32, K/64), block 256.
// ---------------------------------------------------------------------------
__global__ __launch_bounds__(256)
void transpose_cvt_kernel(const float* __restrict__ W, __half* __restrict__ T,
                          int K, int N)
{
    __shared__ float tile[64][33];
    const int t  = threadIdx.x;
    const int tx = t & 31, ty = t >> 5;    // 32 x 8
    const int n0 = blockIdx.x * 32;
    const int k0 = blockIdx.y * 64;

    #pragma unroll
    for (int j = 0; j < 8; j++) {
        int k = ty + j * 8;
        tile[k][tx] = W[(size_t)(k0 + k) * N + n0 + tx];
    }
    __syncthreads();

    // warp ty handles n rows {ty, ty+8, ty+16, ty+24}; lane tx covers k pair
    #pragma unroll
    for (int j = 0; j < 4; j++) {
        int n = ty + j * 8;
        __half2 v = __floats2half2_rn(tile[tx * 2][n], tile[tx * 2 + 1][n]);
        *(__half2*)(T + (size_t)(n0 + n) * K + k0 + tx * 2) = v;
    }
}

// ---------------------------------------------------------------------------
// fp16 GEMM via mma.sync. CTA 128x128, 8 warps (2x4), warp tile 64x32.
// KC=128, 3-stage cp.async (192KB smem, 1 CTA/SM -> 256 regs/thread),
// XOR-swizzled 256B rows, register double-buffered fragments.
// MODE 0: C = A@B^T + bias (*oscale) (+res) (gelu) -> Cf (fp32) or Ch (fp16)
// MODE 1: fused QKV: N=3072 packed; per-1024 segment bias/out/scale.
// ---------------------------------------------------------------------------
#define KC 128
#define TILE_B 32768                     // 128 rows x 256 B
#define STAGE_B (2 * TILE_B)             // 65536
#define GEMM_SMEM (3 * STAGE_B)          // 196608

// 256B rows: 16 chunks of 16B; xor with even value keeps ldmatrix conflict-free
#define SWZ(r, c) ((uint32_t)(r) * 256 + (uint32_t)(((c) ^ (((r) & 7) << 1)) & 15) * 16)

template<int MODE>
__global__ __launch_bounds__(256, 1)
void mma_gemm(const __half* __restrict__ A, const __half* __restrict__ Bm,
              const float* __restrict__ bias, const float* __restrict__ bias2,
              const float* __restrict__ bias3, const float* __restrict__ res,
              float* __restrict__ Cf, __half* __restrict__ Ch,
              __half* __restrict__ Ch2, __half* __restrict__ Ch3,
              int M, int N, int K, int do_gelu, float oscale)
{
    extern __shared__ char sm[];
    const uint32_t sbase = smem_u32(sm);

    const int t    = threadIdx.x;
    const int lane = t & 31;
    const int w    = t >> 5;          // 0..7
    const int wm   = w & 1;           // 2 row groups (64)
    const int wn   = w >> 1;          // 4 col groups (32)
    const int row0 = blockIdx.y * 128;
    const int col0 = blockIdx.x * 128;

    const int NC = K / KC;

    // fragment lane maps
    const int a_r  = wm * 64 + (lane & 15);
    const int a_ch = lane >> 4;                                // 0/1
    const int b_r  = wn * 32 + (lane >> 4) * 8 + (lane & 7);   // + p*16
    const int b_ch = (lane >> 3) & 1;

    float acc[4][4][4];
    #pragma unroll
    for (int i = 0; i < 4; i++)
        #pragma unroll
        for (int j = 0; j < 4; j++)
            #pragma unroll
            for (int e = 0; e < 4; e++) acc[i][j][e] = 0.0f;

    // prologue: chunks 0,1 (per tile: 2048 16B slots, 8 per thread)
    #pragma unroll
    for (int pc = 0; pc < 2; pc++) {
        const int kofs = pc * KC;
        const uint32_t bb = sbase + pc * STAGE_B;
        #pragma unroll
        for (int j = 0; j < 8; j++) {
            int s = j * 256 + t;
            int r = s >> 4, c = s & 15;
            uint32_t sw = SWZ(r, c);
            cp16(bb + sw,          A  + (size_t)(row0 + r) * K + kofs + c * 8);
            cp16(bb + TILE_B + sw, Bm + (size_t)(col0 + r) * K + kofs + c * 8);
        }
        CP_COMMIT();
    }

    uint32_t af[2][4][4];
    uint32_t bf[2][8];

    for (int i = 0; i < NC; i++) {
        CP_WAIT(1);
        __syncthreads();

        if (i + 2 < NC) {
            const int kofs = (i + 2) * KC;
            const uint32_t bb = sbase + ((i + 2) % 3) * STAGE_B;
            #pragma unroll
            for (int j = 0; j < 8; j++) {
                int s = j * 256 + t;
                int r = s >> 4, c = s & 15;
                uint32_t sw = SWZ(r, c);
                cp16(bb + sw,          A  + (size_t)(row0 + r) * K + kofs + c * 8);
                cp16(bb + TILE_B + sw, Bm + (size_t)(col0 + r) * K + kofs + c * 8);
            }
        }
        CP_COMMIT();

        const uint32_t baseA = sbase + (i % 3) * STAGE_B;
        const uint32_t baseB = baseA + TILE_B;

        // preload fragments for ks=0
        #pragma unroll
        for (int p = 0; p < 2; p++)
            ldm_x4(&bf[0][p * 4], baseB + SWZ(b_r + p * 16, b_ch));
        #pragma unroll
        for (int mt = 0; mt < 4; mt++)
            ldm_x4(af[0][mt], baseA + SWZ(a_r + mt * 16, a_ch));

        #pragma unroll
        for (int ks = 0; ks < 8; ks++) {
            const int cur = ks & 1, nxt = cur ^ 1;
            if (ks < 7) {
                #pragma unroll
                for (int p = 0; p < 2; p++)
                    ldm_x4(&bf[nxt][p * 4],
                           baseB + SWZ(b_r + p * 16, (ks + 1) * 2 + b_ch));
                #pragma unroll
                for (int mt = 0; mt < 4; mt++)
                    ldm_x4(af[nxt][mt],
                           baseA + SWZ(a_r + mt * 16, (ks + 1) * 2 + a_ch));
            }
            #pragma unroll
            for (int mt = 0; mt < 4; mt++)
                #pragma unroll
                for (int nt = 0; nt < 4; nt++)
                    mma_f16(acc[mt][nt], af[cur][mt], &bf[cur][nt * 2]);
        }
    }

    // ---- epilogue ----
    const int qr = lane >> 2;
    const int qc = (lane & 3) * 2;

    if (MODE == 1) {
        const int seg = col0 >> 10;                       // 0=Q, 1=K, 2=V
        const float* bseg = (seg == 0) ? bias : (seg == 1) ? bias2 : bias3;
        __half* outp      = (seg == 0) ? Ch   : (seg == 1) ? Ch2   : Ch3;
        const float osc   = (seg == 0) ? 0.125f : 1.0f;
        #pragma unroll
        for (int mt = 0; mt < 4; mt++) {
            #pragma unroll
            for (int nt = 0; nt < 4; nt++) {
                const int gr0 = row0 + wm * 64 + mt * 16 + qr;
                const int gcl = (col0 & 1023) + wn * 32 + nt * 8 + qc;
                float2 bv = *(const float2*)(bseg + gcl);
                *(__half2*)(outp + (size_t)gr0 * HDIM + gcl) =
                    __floats2half2_rn((acc[mt][nt][0] + bv.x) * osc,
                                      (acc[mt][nt][1] + bv.y) * osc);
                *(__half2*)(outp + (size_t)(gr0 + 8) * HDIM + gcl) =
                    __floats2half2_rn((acc[mt][nt][2] + bv.x) * osc,
                                      (acc[mt][nt][3] + bv.y) * osc);
            }
        }
        return;
    }

    #pragma unroll
    for (int mt = 0; mt < 4; mt++) {
        #pragma unroll
        for (int nt = 0; nt < 4; nt++) {
            const int gr0 = row0 + wm * 64 + mt * 16 + qr;
            const int gc  = col0 + wn * 32 + nt * 8 + qc;
            float2 bv = *(const float2*)(bias + gc);
            float o0 = (acc[mt][nt][0] + bv.x) * oscale;
            float o1 = (acc[mt][nt][1] + bv.y) * oscale;
            float o2 = (acc[mt][nt][2] + bv.x) * oscale;
            float o3 = (acc[mt][nt][3] + bv.y) * oscale;
            if (res) {
                float2 r0v = *(const float2*)(res + (size_t)gr0 * N + gc);
                float2 r1v = *(const float2*)(res + (size_t)(gr0 + 8) * N + gc);
                o0 += r0v.x; o1 += r0v.y; o2 += r1v.x; o3 += r1v.y;
            }
            if (do_gelu) {
                o0 = gelu_tanh(o0); o1 = gelu_tanh(o1);
                o2 = gelu_tanh(o2); o3 = gelu_tanh(o3);
            }
            if (Cf) {
                *(float2*)(Cf + (size_t)gr0 * N + gc)       = make_float2(o0, o1);
                *(float2*)(Cf + (size_t)(gr0 + 8) * N + gc) = make_float2(o2, o3);
            } else {
                *(__half2*)(Ch + (size_t)gr0 * N + gc)       = __floats2half2_rn(o0, o1);
                *(__half2*)(Ch + (size_t)(gr0 + 8) * N + gc) = __floats2half2_rn(o2, o3);
            }
        }
    }
}

// ---------------------------------------------------------------------------
// Tensor-core flash attention (fp16 mma, fp32 softmax/accum). Unchanged.
// ---------------------------------------------------------------------------
#define ALDA 72
#define SQ_OFF   0
#define SK_OFF   9216
#define SV_OFF   36864
#define SAD_OFF  64512
#define ATTN_SMEM 89088

__global__ __launch_bounds__(128)
void attn_kernel(const __half* __restrict__ Qg, const __half* __restrict__ Kg,
                 const __half* __restrict__ Vg, const __half* __restrict__ ADg,
                 __half* __restrict__ O)
{
    extern __shared__ char sm[];
    const uint32_t sbase = smem_u32(sm);

    const int t = threadIdx.x;
    const int lane = t & 31;
    const int w = t >> 5;
    const int b = blockIdx.z, h = blockIdx.y;
    const int q0 = blockIdx.x * 64;

    const int qr = lane >> 2;
    const int qc = (lane & 3) * 2;

    const int lr = t >> 1;
    const int lc2 = (t & 1) * 4;

    auto issue = [&](int ic) {
        const int slot = ic % 3;
        const int kc = ic * 64;
        const __half* kg = Kg + (size_t)(b * SEQ + kc + lr) * HDIM + h * DHEAD;
        const __half* vg = Vg + (size_t)(b * SEQ + kc + lr) * HDIM + h * DHEAD;
        const __half* ag = ADg + (size_t)(b * SEQ + q0 + lr) * SEQ + kc;
        uint32_t ks = sbase + SK_OFF + slot * 9216 + lr * (ALDA * 2);
        uint32_t vs = sbase + SV_OFF + slot * 9216 + lr * (ALDA * 2);
        uint32_t as = sbase + SAD_OFF + slot * 8192 + lr * 128;
        #pragma unroll
        for (int c = 0; c < 4; c++) {
            cp16(ks + (lc2 + c) * 16, kg + (lc2 + c) * 8);
            cp16(vs + (lc2 + c) * 16, vg + (lc2 + c) * 8);
            cp16(as + (lc2 + c) * 16, ag + (lc2 + c) * 8);
        }
    };

    {
        const __half* qg = Qg + (size_t)(b * SEQ + q0 + lr) * HDIM + h * DHEAD;
        uint32_t qs = sbase + SQ_OFF + lr * (ALDA * 2);
        #pragma unroll
        for (int c = 0; c < 4; c++)
            cp16(qs + (lc2 + c) * 16, qg + (lc2 + c) * 8);
        issue(0);
        CP_COMMIT();
        issue(1);
        CP_COMMIT();
    }

    const int a_row = w * 16 + (lane & 15);
    const int a_col = (lane >> 4) * 8;
    const int b_nrow = (lane >> 4) * 8 + (lane & 7);
    const int b_kcol = ((lane >> 3) & 1) * 8;
    const int v_krow = lane & 15;
    const int v_ncol = (lane >> 4) * 8;

    uint32_t qf[4][4];
    float Oa[8][4];
    #pragma unroll
    for (int i = 0; i < 8; i++)
        #pragma unroll
        for (int e = 0; e < 4; e++) Oa[i][e] = 0.0f;
    float m0 = -1e30f, m1 = -1e30f, l0 = 0.0f, l1 = 0.0f;

    for (int ic = 0; ic < 8; ic++) {
        CP_WAIT(1);
        __syncthreads();

        if (ic == 0) {
            #pragma unroll
            for (int ks = 0; ks < 4; ks++) {
                uint32_t off = (uint32_t)a_row * (ALDA * 2) + (ks * 16 + a_col) * 2;
                ldm_x4(qf[ks], sbase + SQ_OFF + off);
            }
        }
        if (ic + 2 < 8) issue(ic + 2);
        CP_COMMIT();

        const int slot = ic % 3;
        const uint32_t baseK = sbase + SK_OFF + slot * 9216;
        const uint32_t baseV = sbase + SV_OFF + slot * 9216;
        const uint32_t baseAD = sbase + SAD_OFF + slot * 8192;

        float s[8][4];
        #pragma unroll
        for (int nt = 0; nt < 8; nt++) {
            uint32_t ad0 = (baseAD - sbase) + ((w * 16 + qr) * 64 + nt * 8 + qc) * 2;
            float2 f0 = __half22float2(*(const __half2*)(sm + ad0));
            float2 f1 = __half22float2(*(const __half2*)(sm + ad0 + 8 * 128));
            s[nt][0] = f0.x; s[nt][1] = f0.y;
            s[nt][2] = f1.x; s[nt][3] = f1.y;
        }
        #pragma unroll
        for (int nb = 0; nb < 4; nb++) {
            #pragma unroll
            for (int ks = 0; ks < 4; ks++) {
                uint32_t bfr[4];
                uint32_t off = (uint32_t)(nb * 16 + b_nrow) * (ALDA * 2)
                             + (ks * 16 + b_kcol) * 2;
                ldm_x4(bfr, baseK + off);
                mma_f16(s[2 * nb],     qf[ks], &bfr[0]);
                mma_f16(s[2 * nb + 1], qf[ks], &bfr[2]);
            }
        }

        float mx0 = -1e30f, mx1 = -1e30f;
        #pragma unroll
        for (int nt = 0; nt < 8; nt++) {
            mx0 = fmaxf(mx0, fmaxf(s[nt][0], s[nt][1]));
            mx1 = fmaxf(mx1, fmaxf(s[nt][2], s[nt][3]));
        }
        mx0 = fmaxf(mx0, __shfl_xor_sync(0xffffffffu, mx0, 1));
        mx0 = fmaxf(mx0, __shfl_xor_sync(0xffffffffu, mx0, 2));
        mx1 = fmaxf(mx1, __shfl_xor_sync(0xffffffffu, mx1, 1));
        mx1 = fmaxf(mx1, __shfl_xor_sync(0xffffffffu, mx1, 2));

        const float m0n = fmaxf(m0, mx0);
        const float m1n = fmaxf(m1, mx1);
        const float al0 = __expf(m0 - m0n);
        const float al1 = __expf(m1 - m1n);

        float sum0 = 0.0f, sum1 = 0.0f;
        uint32_t ph[4][4];
        #pragma unroll
        for (int j = 0; j < 4; j++) {
            float p00 = __expf(s[2 * j][0] - m0n);
            float p01 = __expf(s[2 * j][1] - m0n);
            float p02 = __expf(s[2 * j][2] - m1n);
            float p03 = __expf(s[2 * j][3] - m1n);
            float p10 = __expf(s[2 * j + 1][0] - m0n);
            float p11 = __expf(s[2 * j + 1][1] - m0n);
            float p12 = __expf(s[2 * j + 1][2] - m1n);
            float p13 = __expf(s[2 * j + 1][3] - m1n);
            sum0 += p00 + p01 + p10 + p11;
            sum1 += p02 + p03 + p12 + p13;
            ph[j][0] = h2_as_u32(__floats2half2_rn(p00, p01));
            ph[j][1] = h2_as_u32(__floats2half2_rn(p02, p03));
            ph[j][2] = h2_as_u32(__floats2half2_rn(p10, p11));
            ph[j][3] = h2_as_u32(__floats2half2_rn(p12, p13));
        }
        sum0 += __shfl_xor_sync(0xffffffffu, sum0, 1);
        sum0 += __shfl_xor_sync(0xffffffffu, sum0, 2);
        sum1 += __shfl_xor_sync(0xffffffffu, sum1, 1);
        sum1 += __shfl_xor_sync(0xffffffffu, sum1, 2);

        l0 = l0 * al0 + sum0;
        l1 = l1 * al1 + sum1;
        m0 = m0n; m1 = m1n;

        #pragma unroll
        for (int nt = 0; nt < 8; nt++) {
            Oa[nt][0] *= al0; Oa[nt][1] *= al0;
            Oa[nt][2] *= al1; Oa[nt][3] *= al1;
        }

        #pragma unroll
        for (int j = 0; j < 4; j++) {
            #pragma unroll
            for (int nt2 = 0; nt2 < 4; nt2++) {
                uint32_t vf[4];
                uint32_t off = (uint32_t)(j * 16 + v_krow) * (ALDA * 2)
                             + (nt2 * 16 + v_ncol) * 2;
                ldm_x4_t(vf, baseV + off);
                mma_f16(Oa[2 * nt2],     ph[j], &vf[0]);
                mma_f16(Oa[2 * nt2 + 1], ph[j], &vf[2]);
            }
        }
        __syncthreads();
    }

    const float inv0 = 1.0f / l0;
    const float inv1 = 1.0f / l1;
    const int gr0 = b * SEQ + q0 + w * 16 + qr;
    #pragma unroll
    for (int nt = 0; nt < 8; nt++) {
        const int gc = h * DHEAD + nt * 8 + qc;
        *(__half2*)(O + (size_t)gr0 * HDIM + gc) =
            __floats2half2_rn(Oa[nt][0] * inv0, Oa[nt][1] * inv0);
        *(__half2*)(O + (size_t)(gr0 + 8) * HDIM + gc) =
            __floats2half2_rn(Oa[nt][2] * inv1, Oa[nt][3] * inv1);
    }
}

// ---------------------------------------------------------------------------
// LayerNorm over rows of HDIM=1024; optional fp16 dual output.
// ---------------------------------------------------------------------------
__global__ __launch_bounds__(256)
void ln_kernel(const float* __restrict__ x, const float* __restrict__ gamma,
               const float* __restrict__ beta, float* __restrict__ y,
               __half* __restrict__ yh)
{
    const int row = blockIdx.x;
    const int t = threadIdx.x;
    const float* xr = x + (size_t)row * HDIM;

    float4 v = *(const float4*)(xr + t * 4);
    float s  = v.x + v.y + v.z + v.w;
    float s2 = v.x * v.x + v.y * v.y + v.z * v.z + v.w * v.w;

    #pragma unroll
    for (int o = 16; o > 0; o >>= 1) {
        s  += __shfl_xor_sync(0xffffffffu, s, o);
        s2 += __shfl_xor_sync(0xffffffffu, s2, o);
    }
    __shared__ float ws[8], ws2[8];
    const int w = t >> 5, lane = t & 31;
    if (lane == 0) { ws[w] = s; ws2[w] = s2; }
    __syncthreads();

    float ts = 0.0f, ts2 = 0.0f;
    #pragma unroll
    for (int i = 0; i < 8; i++) { ts += ws[i]; ts2 += ws2[i]; }

    const float mean = ts * (1.0f / HDIM);
    const float var  = ts2 * (1.0f / HDIM) - mean * mean;
    const float rstd = rsqrtf(var + 1e-12f);

    float4 g  = *(const float4*)(gamma + t * 4);
    float4 bb = *(const float4*)(beta  + t * 4);
    float4 o;
    o.x = (v.x - mean) * rstd * g.x + bb.x;
    o.y = (v.y - mean) * rstd * g.y + bb.y;
    o.z = (v.z - mean) * rstd * g.z + bb.z;
    o.w = (v.w - mean) * rstd * g.w + bb.w;
    *(float4*)(y + (size_t)row * HDIM + t * 4) = o;
    if (yh) {
        union { __half2 h2[2]; uint2 u; } p;
        p.h2[0] = __floats2half2_rn(o.x, o.y);
        p.h2[1] = __floats2half2_rn(o.z, o.w);
        ((uint2*)(yh + (size_t)row * HDIM))[t] = p.u;
    }
}

// ---------------------------------------------------------------------------
// Orchestration
// ---------------------------------------------------------------------------
extern "C" void kernel_launch(void* const* d_in, const int* in_sizes, int n_in,
                              void* d_out, int out_size)
{
    (void)in_sizes; (void)n_in; (void)out_size;

    const float* inp    = (const float*)d_in[0];
    const int*   mask   = (const int*)  d_in[1];
    const float* Wq     = (const float*)d_in[2];
    const float* bq     = (const float*)d_in[3];
    const float* Wk     = (const float*)d_in[4];
    const float* bk     = (const float*)d_in[5];
    const float* Wv     = (const float*)d_in[6];
    const float* bv     = (const float*)d_in[7];
    const float* Wao    = (const float*)d_in[8];
    const float* bao    = (const float*)d_in[9];
    const float* gamma1 = (const float*)d_in[10];
    const float* beta1  = (const float*)d_in[11];
    const float* Wi     = (const float*)d_in[12];
    const float* bi     = (const float*)d_in[13];
    const float* Wo     = (const float*)d_in[14];
    const float* bo     = (const float*)d_in[15];
    const float* gamma2 = (const float*)d_in[16];
    const float* beta2  = (const float*)d_in[17];
    float* out = (float*)d_out;

    float *t1, *attn;
    cudaGetSymbolAddress((void**)&t1,   g_t1);
    cudaGetSymbolAddress((void**)&attn, g_attn);

    __half *xh, *qh, *kh, *vh, *ctx, *attnh, *inter, *adder;
    __half *wqkv, *wao, *wi, *wo;
    cudaGetSymbolAddress((void**)&xh,    g_xh);
    cudaGetSymbolAddress((void**)&qh,    g_qh);
    cudaGetSymbolAddress((void**)&kh,    g_kh);
    cudaGetSymbolAddress((void**)&vh,    g_vh);
    cudaGetSymbolAddress((void**)&ctx,   g_ctx);
    cudaGetSymbolAddress((void**)&attnh, g_attnh);
    cudaGetSymbolAddress((void**)&inter, g_inter);
    cudaGetSymbolAddress((void**)&adder, g_adder);
    cudaGetSymbolAddress((void**)&wqkv, g_wqkv);
    cudaGetSymbolAddress((void**)&wao,  g_wao);
    cudaGetSymbolAddress((void**)&wi,   g_wi);
    cudaGetSymbolAddress((void**)&wo,   g_wo);

    cudaFuncSetAttribute(mma_gemm<0>, cudaFuncAttributeMaxDynamicSharedMemorySize, GEMM_SMEM);
    cudaFuncSetAttribute(mma_gemm<1>, cudaFuncAttributeMaxDynamicSharedMemorySize, GEMM_SMEM);
    cudaFuncSetAttribute(attn_kernel, cudaFuncAttributeMaxDynamicSharedMemorySize, ATTN_SMEM);

    dim3 blk256(256), blk128(128);
    const int nH4 = MROWS * HDIM / 4;
    const int nM4 = BATCH * SEQ * SEQ / 4;

    dim3 gQKV(3 * HDIM / 128, MROWS / 128);   // 24 x 32
    dim3 gH(HDIM / 128, MROWS / 128);         // 8 x 32
    dim3 gF(FFDIM / 128, MROWS / 128);        // 32 x 32

    // weight transposes: grid (N/32, K/64)
    cvt_kernel<<<(nH4 + 255) / 256, blk256>>>(inp, xh, nH4);
    mask_cvt_kernel<<<(nM4 + 255) / 256, blk256>>>(mask, adder, nM4);
    transpose_cvt_kernel<<<dim3(HDIM/32, HDIM/64), blk256>>>(Wq, wqkv, HDIM, HDIM);
    transpose_cvt_kernel<<<dim3(HDIM/32, HDIM/64), blk256>>>(Wk, wqkv + (size_t)HDIM*HDIM, HDIM, HDIM);
    transpose_cvt_kernel<<<dim3(HDIM/32, HDIM/64), blk256>>>(Wv, wqkv + (size_t)2*HDIM*HDIM, HDIM, HDIM);

    // fused QKV projection
    mma_gemm<1><<<gQKV, blk256, GEMM_SMEM>>>(xh, wqkv, bq, bk, bv, nullptr,
                                             nullptr, qh, kh, vh,
                                             MROWS, 3 * HDIM, HDIM, 0, 1.0f);

    transpose_cvt_kernel<<<dim3(HDIM/32, HDIM/64), blk256>>>(Wao, wao, HDIM, HDIM);
    transpose_cvt_kernel<<<dim3(FFDIM/32, HDIM/64), blk256>>>(Wi, wi, HDIM, FFDIM);
    transpose_cvt_kernel<<<dim3(HDIM/32, FFDIM/64), blk256>>>(Wo, wo, FFDIM, HDIM);

    // tensor-core flash attention -> fp16 ctx
    attn_kernel<<<dim3(SEQ / 64, NHEAD, BATCH), blk128, ATTN_SMEM>>>(qh, kh, vh, adder, ctx);

    // AO projection + residual, LN1
    mma_gemm<0><<<gH, blk256, GEMM_SMEM>>>(ctx, wao, bao, nullptr, nullptr, inp,
                                           t1, nullptr, nullptr, nullptr,
                                           MROWS, HDIM, HDIM, 0, 1.0f);
    ln_kernel<<<MROWS, blk256>>>(t1, gamma1, beta1, attn, attnh);

    // FFN
    mma_gemm<0><<<gF, blk256, GEMM_SMEM>>>(attnh, wi, bi, nullptr, nullptr, nullptr,
                                           nullptr, inter, nullptr, nullptr,
                                           MROWS, FFDIM, HDIM, 1, 1.0f);
    mma_gemm<0><<<gH, blk256, GEMM_SMEM>>>(inter, wo, bo, nullptr, nullptr, attn,
                                           t1, nullptr, nullptr, nullptr,
                                           MROWS, HDIM, FFDIM, 0, 1.0f);
    ln_kernel<<<MROWS, blk256>>>(t1, gamma2, beta2, out, nullptr);
}

// round 10
// speedup vs baseline: 1.2035x; 1.2035x over previous
#include <cuda_runtime.h>
#include <cuda_fp16.h>
#include <math.h>
#include <stdint.h>

#define BATCH 8
#define SEQ   512
#define HDIM  1024
#define FFDIM 4096
#define NHEAD 16
#define DHEAD 64
#define MROWS (BATCH*SEQ)   // 4096

// ---------------------------------------------------------------------------
// Static device scratch
// ---------------------------------------------------------------------------
__device__ float g_t1[(size_t)MROWS * HDIM];
__device__ float g_attn[(size_t)MROWS * HDIM];

__device__ __half g_xh[(size_t)MROWS * HDIM];
__device__ __half g_qh[(size_t)MROWS * HDIM];       // Q (prescaled 0.125)
__device__ __half g_kh[(size_t)MROWS * HDIM];
__device__ __half g_vh[(size_t)MROWS * HDIM];
__device__ __half g_ctx[(size_t)MROWS * HDIM];
__device__ __half g_attnh[(size_t)MROWS * HDIM];
__device__ __half g_inter[(size_t)MROWS * FFDIM];
__device__ __half g_adder[(size_t)BATCH * SEQ * SEQ];

// fp16 weights, K-major [K, N] (QKV packed into [1024, 3072])
__device__ __half g_wqkv[(size_t)HDIM * 3 * HDIM];
__device__ __half g_wao[(size_t)HDIM * HDIM];
__device__ __half g_wi[(size_t)HDIM * FFDIM];
__device__ __half g_wo[(size_t)FFDIM * HDIM];

__device__ __forceinline__ float gelu_tanh(float x) {
    float x3 = x * x * x;
    return 0.5f * x * (1.0f + tanhf(0.7978845608028654f * (x + 0.044715f * x3)));
}
__device__ __forceinline__ uint32_t h2_as_u32(__half2 h) {
    union { __half2 h2; uint32_t u; } c; c.h2 = h; return c.u;
}

// ---------------------------------------------------------------------------
// PTX helpers
// ---------------------------------------------------------------------------
__device__ __forceinline__ uint32_t smem_u32(const void* p) {
    uint32_t a;
    asm("{ .reg .u64 t; cvta.to.shared.u64 t, %1; cvt.u32.u64 %0, t; }"
        : "=r"(a) : "l"(p));
    return a;
}
__device__ __forceinline__ void cp16(uint32_t saddr, const void* gaddr) {
    asm volatile("cp.async.cg.shared.global [%0], [%1], 16;" :: "r"(saddr), "l"(gaddr));
}
#define CP_COMMIT() asm volatile("cp.async.commit_group;" ::: "memory")
#define CP_WAIT(n)  asm volatile("cp.async.wait_group %0;" :: "n"(n) : "memory")

__device__ __forceinline__ void ldm_x4(uint32_t* r, uint32_t addr) {
    asm volatile("ldmatrix.sync.aligned.m8n8.x4.shared.b16 {%0,%1,%2,%3}, [%4];"
        : "=r"(r[0]), "=r"(r[1]), "=r"(r[2]), "=r"(r[3]) : "r"(addr));
}
__device__ __forceinline__ void ldm_x4_t(uint32_t* r, uint32_t addr) {
    asm volatile("ldmatrix.sync.aligned.m8n8.x4.trans.shared.b16 {%0,%1,%2,%3}, [%4];"
        : "=r"(r[0]), "=r"(r[1]), "=r"(r[2]), "=r"(r[3]) : "r"(addr));
}
__device__ __forceinline__ void mma_f16(float* c, const uint32_t* a, const uint32_t* b) {
    asm volatile(
        "mma.sync.aligned.m16n8k16.row.col.f32.f16.f16.f32 "
        "{%0,%1,%2,%3}, {%4,%5,%6,%7}, {%8,%9}, {%0,%1,%2,%3};"
        : "+f"(c[0]), "+f"(c[1]), "+f"(c[2]), "+f"(c[3])
        : "r"(a[0]), "r"(a[1]), "r"(a[2]), "r"(a[3]), "r"(b[0]), "r"(b[1]));
}

// ---------------------------------------------------------------------------
// Elementwise fp32 -> fp16 (straight)
// ---------------------------------------------------------------------------
__global__ __launch_bounds__(256)
void cvt_kernel(const float* __restrict__ x, __half* __restrict__ h, int n4)
{
    int i = blockIdx.x * blockDim.x + threadIdx.x;
    if (i >= n4) return;
    float4 v = ((const float4*)x)[i];
    union { __half2 h2[2]; uint2 u; } p;
    p.h2[0] = __floats2half2_rn(v.x, v.y);
    p.h2[1] = __floats2half2_rn(v.z, v.w);
    ((uint2*)h)[i] = p.u;
}

// fp32 [1024,1024] -> fp16 into packed [1024, 3072] at column seg*1024
__global__ __launch_bounds__(256)
void cvt_qkv_kernel(const float* __restrict__ W, __half* __restrict__ T, int seg)
{
    int i = blockIdx.x * blockDim.x + threadIdx.x;     // 0 .. 1024*1024/4-1
    if (i >= HDIM * HDIM / 4) return;
    int row = i >> 8;                                  // /256
    int col4 = i & 255;
    float4 v = ((const float4*)W)[i];
    union { __half2 h2[2]; uint2 u; } p;
    p.h2[0] = __floats2half2_rn(v.x, v.y);
    p.h2[1] = __floats2half2_rn(v.z, v.w);
    *(uint2*)(T + (size_t)row * 3072 + seg * 1024 + col4 * 4) = p.u;
}

__global__ __launch_bounds__(256)
void mask_cvt_kernel(const int* __restrict__ m, __half* __restrict__ a, int n4)
{
    int i = blockIdx.x * blockDim.x + threadIdx.x;
    if (i >= n4) return;
    int4 v = ((const int4*)m)[i];
    union { __half2 h2[2]; uint2 u; } p;
    p.h2[0] = __floats2half2_rn((1.0f - (float)v.x) * -10000.0f,
                                (1.0f - (float)v.y) * -10000.0f);
    p.h2[1] = __floats2half2_rn((1.0f - (float)v.z) * -10000.0f,
                                (1.0f - (float)v.w) * -10000.0f);
    ((uint2*)a)[i] = p.u;
}

// ---------------------------------------------------------------------------
// fp16 GEMM via mma.sync, B in K-major [K,N] (trans-ldmatrix).
// CTA 128x128, 4 warps (2x2), warp tile 64x64. KC=64, 3-stage cp.async.
// A tile: 128 rows x 128B, XOR swizzle. B tile: 64 k-rows x 272B (16B pad).
// Register double-buffered fragments; launch_bounds(128,2) -> 256 regs/thr.
// MODE 0: C = A@B + bias (*oscale) (+res) (gelu) -> Cf (fp32) or Ch (fp16)
// MODE 1: fused QKV: N=3072 packed; per-1024 segment bias/out/scale.
// ---------------------------------------------------------------------------
#define KC 64
#define A_TILE_B 16384                   // 128 x 128B
#define B_LDS 272                        // 128 cols * 2B + 16B pad
#define B_TILE_B (64 * B_LDS)            // 17408
#define STAGE_B (A_TILE_B + B_TILE_B)    // 33792
#define GEMM_SMEM (3 * STAGE_B)          // 101376

#define SWZ(r, c) ((uint32_t)(r) * 128 + ((uint32_t)((c) ^ ((r) & 7)) * 16))

template<int MODE>
__global__ __launch_bounds__(128, 2)
void mma_gemm(const __half* __restrict__ A, const __half* __restrict__ Bm,
              const float* __restrict__ bias, const float* __restrict__ bias2,
              const float* __restrict__ bias3, const float* __restrict__ res,
              float* __restrict__ Cf, __half* __restrict__ Ch,
              __half* __restrict__ Ch2, __half* __restrict__ Ch3,
              int M, int N, int K, int do_gelu, float oscale)
{
    extern __shared__ char sm[];
    const uint32_t sbase = smem_u32(sm);

    const int t    = threadIdx.x;
    const int lane = t & 31;
    const int w    = t >> 5;          // 0..3
    const int wm   = w & 1;           // 2 row groups (64)
    const int wn   = w >> 1;          // 2 col groups (64)
    const int row0 = blockIdx.y * 128;
    const int col0 = blockIdx.x * 128;

    const int NC = K / KC;

    // A loader: 1024 slots of 16B; 8/thread: r=(s>>3), c=s&7
    // B loader: 1024 slots of 16B; 8/thread: r=(s>>4), c=s&15
    // fragment lane maps
    const int a_r  = wm * 64 + (lane & 15);
    const int a_ch = lane >> 4;                       // c16 = ks*2 + a_ch
    const int b_kr = lane & 15;                       // k within 16-group
    const int b_nc = (lane >> 4) * 8;                 // n offset within 16-group

    float acc[4][8][4];
    #pragma unroll
    for (int i = 0; i < 4; i++)
        #pragma unroll
        for (int j = 0; j < 8; j++)
            #pragma unroll
            for (int e = 0; e < 4; e++) acc[i][j][e] = 0.0f;

    // prologue: chunks 0,1
    #pragma unroll
    for (int pc = 0; pc < 2; pc++) {
        const int kofs = pc * KC;
        const uint32_t bb = sbase + pc * STAGE_B;
        #pragma unroll
        for (int j = 0; j < 8; j++) {
            int s = j * 128 + t;
            int ra = s >> 3, ca = s & 7;
            cp16(bb + SWZ(ra, ca), A + (size_t)(row0 + ra) * K + kofs + ca * 8);
            int rb = s >> 4, cb = s & 15;
            cp16(bb + A_TILE_B + rb * B_LDS + cb * 16,
                 Bm + (size_t)(kofs + rb) * N + col0 + cb * 8);
        }
        CP_COMMIT();
    }

    uint32_t af[2][4][4];
    uint32_t bf[2][16];

    for (int i = 0; i < NC; i++) {
        CP_WAIT(1);
        __syncthreads();

        if (i + 2 < NC) {
            const int kofs = (i + 2) * KC;
            const uint32_t bb = sbase + ((i + 2) % 3) * STAGE_B;
            #pragma unroll
            for (int j = 0; j < 8; j++) {
                int s = j * 128 + t;
                int ra = s >> 3, ca = s & 7;
                cp16(bb + SWZ(ra, ca), A + (size_t)(row0 + ra) * K + kofs + ca * 8);
                int rb = s >> 4, cb = s & 15;
                cp16(bb + A_TILE_B + rb * B_LDS + cb * 16,
                     Bm + (size_t)(kofs + rb) * N + col0 + cb * 8);
            }
        }
        CP_COMMIT();

        const uint32_t baseA = sbase + (i % 3) * STAGE_B;
        const uint32_t baseB = baseA + A_TILE_B;

        // preload fragments for ks=0
        #pragma unroll
        for (int p = 0; p < 4; p++)
            ldm_x4_t(&bf[0][p * 4],
                     baseB + (uint32_t)b_kr * B_LDS
                           + (wn * 64 + p * 16 + b_nc) * 2);
        #pragma unroll
        for (int mt = 0; mt < 4; mt++)
            ldm_x4(af[0][mt], baseA + SWZ(a_r + mt * 16, a_ch));

        #pragma unroll
        for (int ks = 0; ks < 4; ks++) {
            const int cur = ks & 1, nxt = cur ^ 1;
            if (ks < 3) {
                #pragma unroll
                for (int p = 0; p < 4; p++)
                    ldm_x4_t(&bf[nxt][p * 4],
                             baseB + (uint32_t)((ks + 1) * 16 + b_kr) * B_LDS
                                   + (wn * 64 + p * 16 + b_nc) * 2);
                #pragma unroll
                for (int mt = 0; mt < 4; mt++)
                    ldm_x4(af[nxt][mt],
                           baseA + SWZ(a_r + mt * 16, (ks + 1) * 2 + a_ch));
            }
            #pragma unroll
            for (int mt = 0; mt < 4; mt++)
                #pragma unroll
                for (int p = 0; p < 4; p++) {
                    mma_f16(acc[mt][2 * p],     af[cur][mt], &bf[cur][p * 4]);
                    mma_f16(acc[mt][2 * p + 1], af[cur][mt], &bf[cur][p * 4 + 2]);
                }
        }
    }

    // ---- epilogue ----
    const int qr = lane >> 2;
    const int qc = (lane & 3) * 2;

    if (MODE == 1) {
        const int seg = col0 >> 10;                       // 0=Q, 1=K, 2=V
        const float* bseg = (seg == 0) ? bias : (seg == 1) ? bias2 : bias3;
        __half* outp      = (seg == 0) ? Ch   : (seg == 1) ? Ch2   : Ch3;
        const float osc   = (seg == 0) ? 0.125f : 1.0f;
        #pragma unroll
        for (int mt = 0; mt < 4; mt++) {
            #pragma unroll
            for (int nt = 0; nt < 8; nt++) {
                const int gr0 = row0 + wm * 64 + mt * 16 + qr;
                const int gcl = (col0 & 1023) + wn * 64 + nt * 8 + qc;
                float2 bv = *(const float2*)(bseg + gcl);
                *(__half2*)(outp + (size_t)gr0 * HDIM + gcl) =
                    __floats2half2_rn((acc[mt][nt][0] + bv.x) * osc,
                                      (acc[mt][nt][1] + bv.y) * osc);
                *(__half2*)(outp + (size_t)(gr0 + 8) * HDIM + gcl) =
                    __floats2half2_rn((acc[mt][nt][2] + bv.x) * osc,
                                      (acc[mt][nt][3] + bv.y) * osc);
            }
        }
        return;
    }

    #pragma unroll
    for (int mt = 0; mt < 4; mt++) {
        #pragma unroll
        for (int nt = 0; nt < 8; nt++) {
            const int gr0 = row0 + wm * 64 + mt * 16 + qr;
            const int gc  = col0 + wn * 64 + nt * 8 + qc;
            float2 bv = *(const float2*)(bias + gc);
            float o0 = (acc[mt][nt][0] + bv.x) * oscale;
            float o1 = (acc[mt][nt][1] + bv.y) * oscale;
            float o2 = (acc[mt][nt][2] + bv.x) * oscale;
            float o3 = (acc[mt][nt][3] + bv.y) * oscale;
            if (res) {
                float2 r0v = *(const float2*)(res + (size_t)gr0 * N + gc);
                float2 r1v = *(const float2*)(res + (size_t)(gr0 + 8) * N + gc);
                o0 += r0v.x; o1 += r0v.y; o2 += r1v.x; o3 += r1v.y;
            }
            if (do_gelu) {
                o0 = gelu_tanh(o0); o1 = gelu_tanh(o1);
                o2 = gelu_tanh(o2); o3 = gelu_tanh(o3);
            }
            if (Cf) {
                *(float2*)(Cf + (size_t)gr0 * N + gc)       = make_float2(o0, o1);
                *(float2*)(Cf + (size_t)(gr0 + 8) * N + gc) = make_float2(o2, o3);
            } else {
                *(__half2*)(Ch + (size_t)gr0 * N + gc)       = __floats2half2_rn(o0, o1);
                *(__half2*)(Ch + (size_t)(gr0 + 8) * N + gc) = __floats2half2_rn(o2, o3);
            }
        }
    }
}

// ---------------------------------------------------------------------------
// Tensor-core flash attention (fp16 mma, fp32 softmax/accum). Unchanged.
// ---------------------------------------------------------------------------
#define ALDA 72
#define SQ_OFF   0
#define SK_OFF   9216
#define SV_OFF   36864
#define SAD_OFF  64512
#define ATTN_SMEM 89088

__global__ __launch_bounds__(128)
void attn_kernel(const __half* __restrict__ Qg, const __half* __restrict__ Kg,
                 const __half* __restrict__ Vg, const __half* __restrict__ ADg,
                 __half* __restrict__ O)
{
    extern __shared__ char sm[];
    const uint32_t sbase = smem_u32(sm);

    const int t = threadIdx.x;
    const int lane = t & 31;
    const int w = t >> 5;
    const int b = blockIdx.z, h = blockIdx.y;
    const int q0 = blockIdx.x * 64;

    const int qr = lane >> 2;
    const int qc = (lane & 3) * 2;

    const int lr = t >> 1;
    const int lc2 = (t & 1) * 4;

    auto issue = [&](int ic) {
        const int slot = ic % 3;
        const int kc = ic * 64;
        const __half* kg = Kg + (size_t)(b * SEQ + kc + lr) * HDIM + h * DHEAD;
        const __half* vg = Vg + (size_t)(b * SEQ + kc + lr) * HDIM + h * DHEAD;
        const __half* ag = ADg + (size_t)(b * SEQ + q0 + lr) * SEQ + kc;
        uint32_t ks = sbase + SK_OFF + slot * 9216 + lr * (ALDA * 2);
        uint32_t vs = sbase + SV_OFF + slot * 9216 + lr * (ALDA * 2);
        uint32_t as = sbase + SAD_OFF + slot * 8192 + lr * 128;
        #pragma unroll
        for (int c = 0; c < 4; c++) {
            cp16(ks + (lc2 + c) * 16, kg + (lc2 + c) * 8);
            cp16(vs + (lc2 + c) * 16, vg + (lc2 + c) * 8);
            cp16(as + (lc2 + c) * 16, ag + (lc2 + c) * 8);
        }
    };

    {
        const __half* qg = Qg + (size_t)(b * SEQ + q0 + lr) * HDIM + h * DHEAD;
        uint32_t qs = sbase + SQ_OFF + lr * (ALDA * 2);
        #pragma unroll
        for (int c = 0; c < 4; c++)
            cp16(qs + (lc2 + c) * 16, qg + (lc2 + c) * 8);
        issue(0);
        CP_COMMIT();
        issue(1);
        CP_COMMIT();
    }

    const int a_row = w * 16 + (lane & 15);
    const int a_col = (lane >> 4) * 8;
    const int b_nrow = (lane >> 4) * 8 + (lane & 7);
    const int b_kcol = ((lane >> 3) & 1) * 8;
    const int v_krow = lane & 15;
    const int v_ncol = (lane >> 4) * 8;

    uint32_t qf[4][4];
    float Oa[8][4];
    #pragma unroll
    for (int i = 0; i < 8; i++)
        #pragma unroll
        for (int e = 0; e < 4; e++) Oa[i][e] = 0.0f;
    float m0 = -1e30f, m1 = -1e30f, l0 = 0.0f, l1 = 0.0f;

    for (int ic = 0; ic < 8; ic++) {
        CP_WAIT(1);
        __syncthreads();

        if (ic == 0) {
            #pragma unroll
            for (int ks = 0; ks < 4; ks++) {
                uint32_t off = (uint32_t)a_row * (ALDA * 2) + (ks * 16 + a_col) * 2;
                ldm_x4(qf[ks], sbase + SQ_OFF + off);
            }
        }
        if (ic + 2 < 8) issue(ic + 2);
        CP_COMMIT();

        const int slot = ic % 3;
        const uint32_t baseK = sbase + SK_OFF + slot * 9216;
        const uint32_t baseV = sbase + SV_OFF + slot * 9216;
        const uint32_t baseAD = sbase + SAD_OFF + slot * 8192;

        float s[8][4];
        #pragma unroll
        for (int nt = 0; nt < 8; nt++) {
            uint32_t ad0 = (baseAD - sbase) + ((w * 16 + qr) * 64 + nt * 8 + qc) * 2;
            float2 f0 = __half22float2(*(const __half2*)(sm + ad0));
            float2 f1 = __half22float2(*(const __half2*)(sm + ad0 + 8 * 128));
            s[nt][0] = f0.x; s[nt][1] = f0.y;
            s[nt][2] = f1.x; s[nt][3] = f1.y;
        }
        #pragma unroll
        for (int nb = 0; nb < 4; nb++) {
            #pragma unroll
            for (int ks = 0; ks < 4; ks++) {
                uint32_t bfr[4];
                uint32_t off = (uint32_t)(nb * 16 + b_nrow) * (ALDA * 2)
                             + (ks * 16 + b_kcol) * 2;
                ldm_x4(bfr, baseK + off);
                mma_f16(s[2 * nb],     qf[ks], &bfr[0]);
                mma_f16(s[2 * nb + 1], qf[ks], &bfr[2]);
            }
        }

        float mx0 = -1e30f, mx1 = -1e30f;
        #pragma unroll
        for (int nt = 0; nt < 8; nt++) {
            mx0 = fmaxf(mx0, fmaxf(s[nt][0], s[nt][1]));
            mx1 = fmaxf(mx1, fmaxf(s[nt][2], s[nt][3]));
        }
        mx0 = fmaxf(mx0, __shfl_xor_sync(0xffffffffu, mx0, 1));
        mx0 = fmaxf(mx0, __shfl_xor_sync(0xffffffffu, mx0, 2));
        mx1 = fmaxf(mx1, __shfl_xor_sync(0xffffffffu, mx1, 1));
        mx1 = fmaxf(mx1, __shfl_xor_sync(0xffffffffu, mx1, 2));

        const float m0n = fmaxf(m0, mx0);
        const float m1n = fmaxf(m1, mx1);
        const float al0 = __expf(m0 - m0n);
        const float al1 = __expf(m1 - m1n);

        float sum0 = 0.0f, sum1 = 0.0f;
        uint32_t ph[4][4];
        #pragma unroll
        for (int j = 0; j < 4; j++) {
            float p00 = __expf(s[2 * j][0] - m0n);
            float p01 = __expf(s[2 * j][1] - m0n);
            float p02 = __expf(s[2 * j][2] - m1n);
            float p03 = __expf(s[2 * j][3] - m1n);
            float p10 = __expf(s[2 * j + 1][0] - m0n);
            float p11 = __expf(s[2 * j + 1][1] - m0n);
            float p12 = __expf(s[2 * j + 1][2] - m1n);
            float p13 = __expf(s[2 * j + 1][3] - m1n);
            sum0 += p00 + p01 + p10 + p11;
            sum1 += p02 + p03 + p12 + p13;
            ph[j][0] = h2_as_u32(__floats2half2_rn(p00, p01));
            ph[j][1] = h2_as_u32(__floats2half2_rn(p02, p03));
            ph[j][2] = h2_as_u32(__floats2half2_rn(p10, p11));
            ph[j][3] = h2_as_u32(__floats2half2_rn(p12, p13));
        }
        sum0 += __shfl_xor_sync(0xffffffffu, sum0, 1);
        sum0 += __shfl_xor_sync(0xffffffffu, sum0, 2);
        sum1 += __shfl_xor_sync(0xffffffffu, sum1, 1);
        sum1 += __shfl_xor_sync(0xffffffffu, sum1, 2);

        l0 = l0 * al0 + sum0;
        l1 = l1 * al1 + sum1;
        m0 = m0n; m1 = m1n;

        #pragma unroll
        for (int nt = 0; nt < 8; nt++) {
            Oa[nt][0] *= al0; Oa[nt][1] *= al0;
            Oa[nt][2] *= al1; Oa[nt][3] *= al1;
        }

        #pragma unroll
        for (int j = 0; j < 4; j++) {
            #pragma unroll
            for (int nt2 = 0; nt2 < 4; nt2++) {
                uint32_t vf[4];
                uint32_t off = (uint32_t)(j * 16 + v_krow) * (ALDA * 2)
                             + (nt2 * 16 + v_ncol) * 2;
                ldm_x4_t(vf, baseV + off);
                mma_f16(Oa[2 * nt2],     ph[j], &vf[0]);
                mma_f16(Oa[2 * nt2 + 1], ph[j], &vf[2]);
            }
        }
        __syncthreads();
    }

    const float inv0 = 1.0f / l0;
    const float inv1 = 1.0f / l1;
    const int gr0 = b * SEQ + q0 + w * 16 + qr;
    #pragma unroll
    for (int nt = 0; nt < 8; nt++) {
        const int gc = h * DHEAD + nt * 8 + qc;
        *(__half2*)(O + (size_t)gr0 * HDIM + gc) =
            __floats2half2_rn(Oa[nt][0] * inv0, Oa[nt][1] * inv0);
        *(__half2*)(O + (size_t)(gr0 + 8) * HDIM + gc) =
            __floats2half2_rn(Oa[nt][2] * inv1, Oa[nt][3] * inv1);
    }
}

// ---------------------------------------------------------------------------
// LayerNorm over rows of HDIM=1024; optional fp16 dual output.
// ---------------------------------------------------------------------------
__global__ __launch_bounds__(256)
void ln_kernel(const float* __restrict__ x, const float* __restrict__ gamma,
               const float* __restrict__ beta, float* __restrict__ y,
               __half* __restrict__ yh)
{
    const int row = blockIdx.x;
    const int t = threadIdx.x;
    const float* xr = x + (size_t)row * HDIM;

    float4 v = *(const float4*)(xr + t * 4);
    float s  = v.x + v.y + v.z + v.w;
    float s2 = v.x * v.x + v.y * v.y + v.z * v.z + v.w * v.w;

    #pragma unroll
    for (int o = 16; o > 0; o >>= 1) {
        s  += __shfl_xor_sync(0xffffffffu, s, o);
        s2 += __shfl_xor_sync(0xffffffffu, s2, o);
    }
    __shared__ float ws[8], ws2[8];
    const int w = t >> 5, lane = t & 31;
    if (lane == 0) { ws[w] = s; ws2[w] = s2; }
    __syncthreads();

    float ts = 0.0f, ts2 = 0.0f;
    #pragma unroll
    for (int i = 0; i < 8; i++) { ts += ws[i]; ts2 += ws2[i]; }

    const float mean = ts * (1.0f / HDIM);
    const float var  = ts2 * (1.0f / HDIM) - mean * mean;
    const float rstd = rsqrtf(var + 1e-12f);

    float4 g  = *(const float4*)(gamma + t * 4);
    float4 bb = *(const float4*)(beta  + t * 4);
    float4 o;
    o.x = (v.x - mean) * rstd * g.x + bb.x;
    o.y = (v.y - mean) * rstd * g.y + bb.y;
    o.z = (v.z - mean) * rstd * g.z + bb.z;
    o.w = (v.w - mean) * rstd * g.w + bb.w;
    *(float4*)(y + (size_t)row * HDIM + t * 4) = o;
    if (yh) {
        union { __half2 h2[2]; uint2 u; } p;
        p.h2[0] = __floats2half2_rn(o.x, o.y);
        p.h2[1] = __floats2half2_rn(o.z, o.w);
        ((uint2*)(yh + (size_t)row * HDIM))[t] = p.u;
    }
}

// ---------------------------------------------------------------------------
// Orchestration
// ---------------------------------------------------------------------------
extern "C" void kernel_launch(void* const* d_in, const int* in_sizes, int n_in,
                              void* d_out, int out_size)
{
    (void)in_sizes; (void)n_in; (void)out_size;

    const float* inp    = (const float*)d_in[0];
    const int*   mask   = (const int*)  d_in[1];
    const float* Wq     = (const float*)d_in[2];
    const float* bq     = (const float*)d_in[3];
    const float* Wk     = (const float*)d_in[4];
    const float* bk     = (const float*)d_in[5];
    const float* Wv     = (const float*)d_in[6];
    const float* bv     = (const float*)d_in[7];
    const float* Wao    = (const float*)d_in[8];
    const float* bao    = (const float*)d_in[9];
    const float* gamma1 = (const float*)d_in[10];
    const float* beta1  = (const float*)d_in[11];
    const float* Wi     = (const float*)d_in[12];
    const float* bi     = (const float*)d_in[13];
    const float* Wo     = (const float*)d_in[14];
    const float* bo     = (const float*)d_in[15];
    const float* gamma2 = (const float*)d_in[16];
    const float* beta2  = (const float*)d_in[17];
    float* out = (float*)d_out;

    float *t1, *attn;
    cudaGetSymbolAddress((void**)&t1,   g_t1);
    cudaGetSymbolAddress((void**)&attn, g_attn);

    __half *xh, *qh, *kh, *vh, *ctx, *attnh, *inter, *adder;
    __half *wqkv, *wao, *wi, *wo;
    cudaGetSymbolAddress((void**)&xh,    g_xh);
    cudaGetSymbolAddress((void**)&qh,    g_qh);
    cudaGetSymbolAddress((void**)&kh,    g_kh);
    cudaGetSymbolAddress((void**)&vh,    g_vh);
    cudaGetSymbolAddress((void**)&ctx,   g_ctx);
    cudaGetSymbolAddress((void**)&attnh, g_attnh);
    cudaGetSymbolAddress((void**)&inter, g_inter);
    cudaGetSymbolAddress((void**)&adder, g_adder);
    cudaGetSymbolAddress((void**)&wqkv, g_wqkv);
    cudaGetSymbolAddress((void**)&wao,  g_wao);
    cudaGetSymbolAddress((void**)&wi,   g_wi);
    cudaGetSymbolAddress((void**)&wo,   g_wo);

    cudaFuncSetAttribute(mma_gemm<0>, cudaFuncAttributeMaxDynamicSharedMemorySize, GEMM_SMEM);
    cudaFuncSetAttribute(mma_gemm<1>, cudaFuncAttributeMaxDynamicSharedMemorySize, GEMM_SMEM);
    cudaFuncSetAttribute(attn_kernel, cudaFuncAttributeMaxDynamicSharedMemorySize, ATTN_SMEM);

    dim3 blk256(256), blk128(128);
    const int nH4 = MROWS * HDIM / 4;
    const int nM4 = BATCH * SEQ * SEQ / 4;
    const int nW4 = HDIM * HDIM / 4;
    const int nWF4 = HDIM * FFDIM / 4;

    dim3 gQKV(3 * HDIM / 128, MROWS / 128);   // 24 x 32
    dim3 gH(HDIM / 128, MROWS / 128);         // 8 x 32
    dim3 gF(FFDIM / 128, MROWS / 128);        // 32 x 32

    // launches 1-5 so #6 (profiled) = fused QKV GEMM
    cvt_kernel<<<(nH4 + 255) / 256, blk256>>>(inp, xh, nH4);                   // 1
    mask_cvt_kernel<<<(nM4 + 255) / 256, blk256>>>(mask, adder, nM4);          // 2
    cvt_qkv_kernel<<<(nW4 + 255) / 256, blk256>>>(Wq, wqkv, 0);                // 3
    cvt_qkv_kernel<<<(nW4 + 255) / 256, blk256>>>(Wk, wqkv, 1);                // 4
    cvt_qkv_kernel<<<(nW4 + 255) / 256, blk256>>>(Wv, wqkv, 2);                // 5

    // fused QKV projection (B = [1024, 3072] K-major)
    mma_gemm<1><<<gQKV, blk128, GEMM_SMEM>>>(xh, wqkv, bq, bk, bv, nullptr,
                                             nullptr, qh, kh, vh,
                                             MROWS, 3 * HDIM, HDIM, 0, 1.0f);

    cvt_kernel<<<(nW4 + 255) / 256, blk256>>>(Wao, wao, nW4);
    cvt_kernel<<<(nWF4 + 255) / 256, blk256>>>(Wi, wi, nWF4);
    cvt_kernel<<<(nWF4 + 255) / 256, blk256>>>(Wo, wo, nWF4);

    // tensor-core flash attention -> fp16 ctx
    attn_kernel<<<dim3(SEQ / 64, NHEAD, BATCH), blk128, ATTN_SMEM>>>(qh, kh, vh, adder, ctx);

    // AO projection + residual, LN1
    mma_gemm<0><<<gH, blk128, GEMM_SMEM>>>(ctx, wao, bao, nullptr, nullptr, inp,
                                           t1, nullptr, nullptr, nullptr,
                                           MROWS, HDIM, HDIM, 0, 1.0f);
    ln_kernel<<<MROWS, blk256>>>(t1, gamma1, beta1, attn, attnh);

    // FFN
    mma_gemm<0><<<gF, blk128, GEMM_SMEM>>>(attnh, wi, bi, nullptr, nullptr, nullptr,
                                           nullptr, inter, nullptr, nullptr,
                                           MROWS, FFDIM, HDIM, 1, 1.0f);
    mma_gemm<0><<<gH, blk128, GEMM_SMEM>>>(inter, wo, bo, nullptr, nullptr, attn,
                                           t1, nullptr, nullptr, nullptr,
                                           MROWS, HDIM, FFDIM, 0, 1.0f);
    ln_kernel<<<MROWS, blk256>>>(t1, gamma2, beta2, out, nullptr);
}

// round 11
// speedup vs baseline: 1.2891x; 1.0711x over previous
#include <cuda_runtime.h>
#include <cuda_fp16.h>
#include <math.h>
#include <stdint.h>

#define BATCH 8
#define SEQ   512
#define HDIM  1024
#define FFDIM 4096
#define NHEAD 16
#define DHEAD 64
#define MROWS (BATCH*SEQ)   // 4096

// ---------------------------------------------------------------------------
// Static device scratch
// ---------------------------------------------------------------------------
__device__ float g_t1[(size_t)MROWS * HDIM];
__device__ float g_attn[(size_t)MROWS * HDIM];

__device__ __half g_xh[(size_t)MROWS * HDIM];
__device__ __half g_qh[(size_t)MROWS * HDIM];       // Q (prescaled 0.125)
__device__ __half g_kh[(size_t)MROWS * HDIM];
__device__ __half g_vh[(size_t)MROWS * HDIM];
__device__ __half g_ctx[(size_t)MROWS * HDIM];
__device__ __half g_attnh[(size_t)MROWS * HDIM];
__device__ __half g_inter[(size_t)MROWS * FFDIM];
__device__ __half g_adder[(size_t)BATCH * SEQ * SEQ];

__device__ __half g_wqkv[(size_t)3 * HDIM * HDIM];  // packed, transposed [N,K]
__device__ __half g_wao[(size_t)HDIM * HDIM];
__device__ __half g_wi[(size_t)FFDIM * HDIM];
__device__ __half g_wo[(size_t)HDIM * FFDIM];

__device__ __forceinline__ float gelu_tanh(float x) {
    float x3 = x * x * x;
    return 0.5f * x * (1.0f + tanhf(0.7978845608028654f * (x + 0.044715f * x3)));
}
__device__ __forceinline__ uint32_t h2_as_u32(__half2 h) {
    union { __half2 h2; uint32_t u; } c; c.h2 = h; return c.u;
}

// ---------------------------------------------------------------------------
// PTX helpers
// ---------------------------------------------------------------------------
__device__ __forceinline__ uint32_t smem_u32(const void* p) {
    uint32_t a;
    asm("{ .reg .u64 t; cvta.to.shared.u64 t, %1; cvt.u32.u64 %0, t; }"
        : "=r"(a) : "l"(p));
    return a;
}
__device__ __forceinline__ void cp16(uint32_t saddr, const void* gaddr) {
    asm volatile("cp.async.cg.shared.global [%0], [%1], 16;" :: "r"(saddr), "l"(gaddr));
}
#define CP_COMMIT() asm volatile("cp.async.commit_group;" ::: "memory")
#define CP_WAIT(n)  asm volatile("cp.async.wait_group %0;" :: "n"(n) : "memory")

__device__ __forceinline__ void ldm_x4(uint32_t* r, uint32_t addr) {
    asm volatile("ldmatrix.sync.aligned.m8n8.x4.shared.b16 {%0,%1,%2,%3}, [%4];"
        : "=r"(r[0]), "=r"(r[1]), "=r"(r[2]), "=r"(r[3]) : "r"(addr));
}
__device__ __forceinline__ void ldm_x4_t(uint32_t* r, uint32_t addr) {
    asm volatile("ldmatrix.sync.aligned.m8n8.x4.trans.shared.b16 {%0,%1,%2,%3}, [%4];"
        : "=r"(r[0]), "=r"(r[1]), "=r"(r[2]), "=r"(r[3]) : "r"(addr));
}
__device__ __forceinline__ void mma_f16(float* c, const uint32_t* a, const uint32_t* b) {
    asm volatile(
        "mma.sync.aligned.m16n8k16.row.col.f32.f16.f16.f32 "
        "{%0,%1,%2,%3}, {%4,%5,%6,%7}, {%8,%9}, {%0,%1,%2,%3};"
        : "+f"(c[0]), "+f"(c[1]), "+f"(c[2]), "+f"(c[3])
        : "r"(a[0]), "r"(a[1]), "r"(a[2]), "r"(a[3]), "r"(b[0]), "r"(b[1]));
}

// ---------------------------------------------------------------------------
// Elementwise fp32 -> fp16
// ---------------------------------------------------------------------------
__global__ __launch_bounds__(256)
void cvt_kernel(const float* __restrict__ x, __half* __restrict__ h, int n4)
{
    int i = blockIdx.x * blockDim.x + threadIdx.x;
    if (i >= n4) return;
    float4 v = ((const float4*)x)[i];
    union { __half2 h2[2]; uint2 u; } p;
    p.h2[0] = __floats2half2_rn(v.x, v.y);
    p.h2[1] = __floats2half2_rn(v.z, v.w);
    ((uint2*)h)[i] = p.u;
}

__global__ __launch_bounds__(256)
void mask_cvt_kernel(const int* __restrict__ m, __half* __restrict__ a, int n4)
{
    int i = blockIdx.x * blockDim.x + threadIdx.x;
    if (i >= n4) return;
    int4 v = ((const int4*)m)[i];
    union { __half2 h2[2]; uint2 u; } p;
    p.h2[0] = __floats2half2_rn((1.0f - (float)v.x) * -10000.0f,
                                (1.0f - (float)v.y) * -10000.0f);
    p.h2[1] = __floats2half2_rn((1.0f - (float)v.z) * -10000.0f,
                                (1.0f - (float)v.w) * -10000.0f);
    ((uint2*)a)[i] = p.u;
}

// ---------------------------------------------------------------------------
// W[K,N] fp32 -> T[N,K] fp16, v2: 64x64 tile, float4 reads, 128B half2 writes.
// grid: (N/64, K/64), block 256.
// ---------------------------------------------------------------------------
__global__ __launch_bounds__(256)
void transpose_cvt_kernel(const float* __restrict__ W, __half* __restrict__ T,
                          int K, int N)
{
    __shared__ float tile[64][65];
    const int t  = threadIdx.x;
    const int n0 = blockIdx.x * 64;
    const int k0 = blockIdx.y * 64;

    // read: 16x16 thread grid, each thread 4 float4 rows
    const int rx = t & 15;        // float4 column (0..15)
    const int ry = t >> 4;        // row base (0..15)
    #pragma unroll
    for (int j = 0; j < 4; j++) {
        int r = ry + j * 16;
        float4 v = *(const float4*)(W + (size_t)(k0 + r) * N + n0 + rx * 4);
        tile[r][rx * 4 + 0] = v.x;
        tile[r][rx * 4 + 1] = v.y;
        tile[r][rx * 4 + 2] = v.z;
        tile[r][rx * 4 + 3] = v.w;
    }
    __syncthreads();

    // write: warp (t>>5) handles n rows {w, w+8, ..., w+56}; lane covers k pair
    const int lane = t & 31;
    const int wy   = t >> 5;
    #pragma unroll
    for (int j = 0; j < 8; j++) {
        int n = wy + j * 8;
        __half2 v = __floats2half2_rn(tile[lane * 2][n], tile[lane * 2 + 1][n]);
        *(__half2*)(T + (size_t)(n0 + n) * K + k0 + lane * 2) = v;
    }
}

// ---------------------------------------------------------------------------
// fp16 GEMM via mma.sync (R8 config). CTA 128x128, 4 warps (2x2), warp 64x64.
// KC=64, 3-stage cp.async, XOR-swizzled 128B rows, reg double-buffered frags.
// launch_bounds(128,2) -> 256 regs/thread, 2 CTA/SM.
// MODE 0: C = A@B^T + bias (*oscale) (+res) (gelu) -> Cf (fp32) or Ch (fp16)
// MODE 1: fused QKV: N=3072 packed; per-1024 segment bias/out/scale.
// ---------------------------------------------------------------------------
#define KC 64
#define TILE_B 16384                     // 128 rows x 128 B
#define STAGE_B (2 * TILE_B)             // 32768
#define GEMM_SMEM (3 * STAGE_B)          // 98304

#define SWZ(r, c) ((uint32_t)(r) * 128 + ((uint32_t)((c) ^ ((r) & 7)) * 16))

template<int MODE>
__global__ __launch_bounds__(128, 2)
void mma_gemm(const __half* __restrict__ A, const __half* __restrict__ Bm,
              const float* __restrict__ bias, const float* __restrict__ bias2,
              const float* __restrict__ bias3, const float* __restrict__ res,
              float* __restrict__ Cf, __half* __restrict__ Ch,
              __half* __restrict__ Ch2, __half* __restrict__ Ch3,
              int M, int N, int K, int do_gelu, float oscale)
{
    extern __shared__ char sm[];
    const uint32_t sbase = smem_u32(sm);

    const int t    = threadIdx.x;
    const int lane = t & 31;
    const int w    = t >> 5;          // 0..3
    const int wm   = w & 1;           // 2 row groups (64)
    const int wn   = w >> 1;          // 2 col groups (64)
    const int row0 = blockIdx.y * 128;
    const int col0 = blockIdx.x * 128;

    const int NC = K / KC;

    // loader: per tile 1024 x 16B slots; 8 per thread: r = (t>>3) + j*16, c = t&7
    const int l_r = t >> 3;
    const int l_c = t & 7;

    // fragment lane maps
    const int a_r  = wm * 64 + (lane & 15);
    const int a_ch = lane >> 4;
    const int b_r  = wn * 64 + (lane >> 4) * 8 + (lane & 7);   // + p*16
    const int b_ch = (lane >> 3) & 1;

    float acc[4][8][4];
    #pragma unroll
    for (int i = 0; i < 4; i++)
        #pragma unroll
        for (int j = 0; j < 8; j++)
            #pragma unroll
            for (int e = 0; e < 4; e++) acc[i][j][e] = 0.0f;

    // prologue: chunks 0,1
    #pragma unroll
    for (int pc = 0; pc < 2; pc++) {
        const int kofs = pc * KC;
        const uint32_t bb = sbase + pc * STAGE_B;
        #pragma unroll
        for (int j = 0; j < 8; j++) {
            int r = l_r + j * 16;
            uint32_t sw = SWZ(r, l_c);
            cp16(bb + sw,          A  + (size_t)(row0 + r) * K + kofs + l_c * 8);
            cp16(bb + TILE_B + sw, Bm + (size_t)(col0 + r) * K + kofs + l_c * 8);
        }
        CP_COMMIT();
    }

    uint32_t af[2][4][4];   // [buf][mt][frag]
    uint32_t bf[2][16];     // [buf][nt pairs]

    for (int i = 0; i < NC; i++) {
        CP_WAIT(1);
        __syncthreads();

        if (i + 2 < NC) {
            const int kofs = (i + 2) * KC;
            const uint32_t bb = sbase + ((i + 2) % 3) * STAGE_B;
            #pragma unroll
            for (int j = 0; j < 8; j++) {
                int r = l_r + j * 16;
                uint32_t sw = SWZ(r, l_c);
                cp16(bb + sw,          A  + (size_t)(row0 + r) * K + kofs + l_c * 8);
                cp16(bb + TILE_B + sw, Bm + (size_t)(col0 + r) * K + kofs + l_c * 8);
            }
        }
        CP_COMMIT();

        const uint32_t baseA = sbase + (i % 3) * STAGE_B;
        const uint32_t baseB = baseA + TILE_B;

        // preload fragments for ks=0
        #pragma unroll
        for (int p = 0; p < 4; p++)
            ldm_x4(&bf[0][p * 4], baseB + SWZ(b_r + p * 16, b_ch));
        #pragma unroll
        for (int mt = 0; mt < 4; mt++)
            ldm_x4(af[0][mt], baseA + SWZ(a_r + mt * 16, a_ch));

        #pragma unroll
        for (int ks = 0; ks < 4; ks++) {
            const int cur = ks & 1, nxt = cur ^ 1;
            if (ks < 3) {
                #pragma unroll
                for (int p = 0; p < 4; p++)
                    ldm_x4(&bf[nxt][p * 4],
                           baseB + SWZ(b_r + p * 16, (ks + 1) * 2 + b_ch));
                #pragma unroll
                for (int mt = 0; mt < 4; mt++)
                    ldm_x4(af[nxt][mt],
                           baseA + SWZ(a_r + mt * 16, (ks + 1) * 2 + a_ch));
            }
            #pragma unroll
            for (int mt = 0; mt < 4; mt++)
                #pragma unroll
                for (int nt = 0; nt < 8; nt++)
                    mma_f16(acc[mt][nt], af[cur][mt], &bf[cur][nt * 2]);
        }
    }

    // ---- epilogue ----
    const int qr = lane >> 2;
    const int qc = (lane & 3) * 2;

    if (MODE == 1) {
        const int seg = col0 >> 10;                       // 0=Q, 1=K, 2=V
        const float* bseg = (seg == 0) ? bias : (seg == 1) ? bias2 : bias3;
        __half* outp      = (seg == 0) ? Ch   : (seg == 1) ? Ch2   : Ch3;
        const float osc   = (seg == 0) ? 0.125f : 1.0f;
        #pragma unroll
        for (int mt = 0; mt < 4; mt++) {
            #pragma unroll
            for (int nt = 0; nt < 8; nt++) {
                const int gr0 = row0 + wm * 64 + mt * 16 + qr;
                const int gcl = (col0 & 1023) + wn * 64 + nt * 8 + qc;
                float2 bv = *(const float2*)(bseg + gcl);
                *(__half2*)(outp + (size_t)gr0 * HDIM + gcl) =
                    __floats2half2_rn((acc[mt][nt][0] + bv.x) * osc,
                                      (acc[mt][nt][1] + bv.y) * osc);
                *(__half2*)(outp + (size_t)(gr0 + 8) * HDIM + gcl) =
                    __floats2half2_rn((acc[mt][nt][2] + bv.x) * osc,
                                      (acc[mt][nt][3] + bv.y) * osc);
            }
        }
        return;
    }

    #pragma unroll
    for (int mt = 0; mt < 4; mt++) {
        #pragma unroll
        for (int nt = 0; nt < 8; nt++) {
            const int gr0 = row0 + wm * 64 + mt * 16 + qr;
            const int gc  = col0 + wn * 64 + nt * 8 + qc;
            float2 bv = *(const float2*)(bias + gc);
            float o0 = (acc[mt][nt][0] + bv.x) * oscale;
            float o1 = (acc[mt][nt][1] + bv.y) * oscale;
            float o2 = (acc[mt][nt][2] + bv.x) * oscale;
            float o3 = (acc[mt][nt][3] + bv.y) * oscale;
            if (res) {
                float2 r0v = *(const float2*)(res + (size_t)gr0 * N + gc);
                float2 r1v = *(const float2*)(res + (size_t)(gr0 + 8) * N + gc);
                o0 += r0v.x; o1 += r0v.y; o2 += r1v.x; o3 += r1v.y;
            }
            if (do_gelu) {
                o0 = gelu_tanh(o0); o1 = gelu_tanh(o1);
                o2 = gelu_tanh(o2); o3 = gelu_tanh(o3);
            }
            if (Cf) {
                *(float2*)(Cf + (size_t)gr0 * N + gc)       = make_float2(o0, o1);
                *(float2*)(Cf + (size_t)(gr0 + 8) * N + gc) = make_float2(o2, o3);
            } else {
                *(__half2*)(Ch + (size_t)gr0 * N + gc)       = __floats2half2_rn(o0, o1);
                *(__half2*)(Ch + (size_t)(gr0 + 8) * N + gc) = __floats2half2_rn(o2, o3);
            }
        }
    }
}

// ---------------------------------------------------------------------------
// Tensor-core flash attention (fp16 mma, fp32 softmax/accum). Unchanged.
// ---------------------------------------------------------------------------
#define ALDA 72
#define SQ_OFF   0
#define SK_OFF   9216
#define SV_OFF   36864
#define SAD_OFF  64512
#define ATTN_SMEM 89088

__global__ __launch_bounds__(128)
void attn_kernel(const __half* __restrict__ Qg, const __half* __restrict__ Kg,
                 const __half* __restrict__ Vg, const __half* __restrict__ ADg,
                 __half* __restrict__ O)
{
    extern __shared__ char sm[];
    const uint32_t sbase = smem_u32(sm);

    const int t = threadIdx.x;
    const int lane = t & 31;
    const int w = t >> 5;
    const int b = blockIdx.z, h = blockIdx.y;
    const int q0 = blockIdx.x * 64;

    const int qr = lane >> 2;
    const int qc = (lane & 3) * 2;

    const int lr = t >> 1;
    const int lc2 = (t & 1) * 4;

    auto issue = [&](int ic) {
        const int slot = ic % 3;
        const int kc = ic * 64;
        const __half* kg = Kg + (size_t)(b * SEQ + kc + lr) * HDIM + h * DHEAD;
        const __half* vg = Vg + (size_t)(b * SEQ + kc + lr) * HDIM + h * DHEAD;
        const __half* ag = ADg + (size_t)(b * SEQ + q0 + lr) * SEQ + kc;
        uint32_t ks = sbase + SK_OFF + slot * 9216 + lr * (ALDA * 2);
        uint32_t vs = sbase + SV_OFF + slot * 9216 + lr * (ALDA * 2);
        uint32_t as = sbase + SAD_OFF + slot * 8192 + lr * 128;
        #pragma unroll
        for (int c = 0; c < 4; c++) {
            cp16(ks + (lc2 + c) * 16, kg + (lc2 + c) * 8);
            cp16(vs + (lc2 + c) * 16, vg + (lc2 + c) * 8);
            cp16(as + (lc2 + c) * 16, ag + (lc2 + c) * 8);
        }
    };

    {
        const __half* qg = Qg + (size_t)(b * SEQ + q0 + lr) * HDIM + h * DHEAD;
        uint32_t qs = sbase + SQ_OFF + lr * (ALDA * 2);
        #pragma unroll
        for (int c = 0; c < 4; c++)
            cp16(qs + (lc2 + c) * 16, qg + (lc2 + c) * 8);
        issue(0);
        CP_COMMIT();
        issue(1);
        CP_COMMIT();
    }

    const int a_row = w * 16 + (lane & 15);
    const int a_col = (lane >> 4) * 8;
    const int b_nrow = (lane >> 4) * 8 + (lane & 7);
    const int b_kcol = ((lane >> 3) & 1) * 8;
    const int v_krow = lane & 15;
    const int v_ncol = (lane >> 4) * 8;

    uint32_t qf[4][4];
    float Oa[8][4];
    #pragma unroll
    for (int i = 0; i < 8; i++)
        #pragma unroll
        for (int e = 0; e < 4; e++) Oa[i][e] = 0.0f;
    float m0 = -1e30f, m1 = -1e30f, l0 = 0.0f, l1 = 0.0f;

    for (int ic = 0; ic < 8; ic++) {
        CP_WAIT(1);
        __syncthreads();

        if (ic == 0) {
            #pragma unroll
            for (int ks = 0; ks < 4; ks++) {
                uint32_t off = (uint32_t)a_row * (ALDA * 2) + (ks * 16 + a_col) * 2;
                ldm_x4(qf[ks], sbase + SQ_OFF + off);
            }
        }
        if (ic + 2 < 8) issue(ic + 2);
        CP_COMMIT();

        const int slot = ic % 3;
        const uint32_t baseK = sbase + SK_OFF + slot * 9216;
        const uint32_t baseV = sbase + SV_OFF + slot * 9216;
        const uint32_t baseAD = sbase + SAD_OFF + slot * 8192;

        float s[8][4];
        #pragma unroll
        for (int nt = 0; nt < 8; nt++) {
            uint32_t ad0 = (baseAD - sbase) + ((w * 16 + qr) * 64 + nt * 8 + qc) * 2;
            float2 f0 = __half22float2(*(const __half2*)(sm + ad0));
            float2 f1 = __half22float2(*(const __half2*)(sm + ad0 + 8 * 128));
            s[nt][0] = f0.x; s[nt][1] = f0.y;
            s[nt][2] = f1.x; s[nt][3] = f1.y;
        }
        #pragma unroll
        for (int nb = 0; nb < 4; nb++) {
            #pragma unroll
            for (int ks = 0; ks < 4; ks++) {
                uint32_t bfr[4];
                uint32_t off = (uint32_t)(nb * 16 + b_nrow) * (ALDA * 2)
                             + (ks * 16 + b_kcol) * 2;
                ldm_x4(bfr, baseK + off);
                mma_f16(s[2 * nb],     qf[ks], &bfr[0]);
                mma_f16(s[2 * nb + 1], qf[ks], &bfr[2]);
            }
        }

        float mx0 = -1e30f, mx1 = -1e30f;
        #pragma unroll
        for (int nt = 0; nt < 8; nt++) {
            mx0 = fmaxf(mx0, fmaxf(s[nt][0], s[nt][1]));
            mx1 = fmaxf(mx1, fmaxf(s[nt][2], s[nt][3]));
        }
        mx0 = fmaxf(mx0, __shfl_xor_sync(0xffffffffu, mx0, 1));
        mx0 = fmaxf(mx0, __shfl_xor_sync(0xffffffffu, mx0, 2));
        mx1 = fmaxf(mx1, __shfl_xor_sync(0xffffffffu, mx1, 1));
        mx1 = fmaxf(mx1, __shfl_xor_sync(0xffffffffu, mx1, 2));

        const float m0n = fmaxf(m0, mx0);
        const float m1n = fmaxf(m1, mx1);
        const float al0 = __expf(m0 - m0n);
        const float al1 = __expf(m1 - m1n);

        float sum0 = 0.0f, sum1 = 0.0f;
        uint32_t ph[4][4];
        #pragma unroll
        for (int j = 0; j < 4; j++) {
            float p00 = __expf(s[2 * j][0] - m0n);
            float p01 = __expf(s[2 * j][1] - m0n);
            float p02 = __expf(s[2 * j][2] - m1n);
            float p03 = __expf(s[2 * j][3] - m1n);
            float p10 = __expf(s[2 * j + 1][0] - m0n);
            float p11 = __expf(s[2 * j + 1][1] - m0n);
            float p12 = __expf(s[2 * j + 1][2] - m1n);
            float p13 = __expf(s[2 * j + 1][3] - m1n);
            sum0 += p00 + p01 + p10 + p11;
            sum1 += p02 + p03 + p12 + p13;
            ph[j][0] = h2_as_u32(__floats2half2_rn(p00, p01));
            ph[j][1] = h2_as_u32(__floats2half2_rn(p02, p03));
            ph[j][2] = h2_as_u32(__floats2half2_rn(p10, p11));
            ph[j][3] = h2_as_u32(__floats2half2_rn(p12, p13));
        }
        sum0 += __shfl_xor_sync(0xffffffffu, sum0, 1);
        sum0 += __shfl_xor_sync(0xffffffffu, sum0, 2);
        sum1 += __shfl_xor_sync(0xffffffffu, sum1, 1);
        sum1 += __shfl_xor_sync(0xffffffffu, sum1, 2);

        l0 = l0 * al0 + sum0;
        l1 = l1 * al1 + sum1;
        m0 = m0n; m1 = m1n;

        #pragma unroll
        for (int nt = 0; nt < 8; nt++) {
            Oa[nt][0] *= al0; Oa[nt][1] *= al0;
            Oa[nt][2] *= al1; Oa[nt][3] *= al1;
        }

        #pragma unroll
        for (int j = 0; j < 4; j++) {
            #pragma unroll
            for (int nt2 = 0; nt2 < 4; nt2++) {
                uint32_t vf[4];
                uint32_t off = (uint32_t)(j * 16 + v_krow) * (ALDA * 2)
                             + (nt2 * 16 + v_ncol) * 2;
                ldm_x4_t(vf, baseV + off);
                mma_f16(Oa[2 * nt2],     ph[j], &vf[0]);
                mma_f16(Oa[2 * nt2 + 1], ph[j], &vf[2]);
            }
        }
        __syncthreads();
    }

    const float inv0 = 1.0f / l0;
    const float inv1 = 1.0f / l1;
    const int gr0 = b * SEQ + q0 + w * 16 + qr;
    #pragma unroll
    for (int nt = 0; nt < 8; nt++) {
        const int gc = h * DHEAD + nt * 8 + qc;
        *(__half2*)(O + (size_t)gr0 * HDIM + gc) =
            __floats2half2_rn(Oa[nt][0] * inv0, Oa[nt][1] * inv0);
        *(__half2*)(O + (size_t)(gr0 + 8) * HDIM + gc) =
            __floats2half2_rn(Oa[nt][2] * inv1, Oa[nt][3] * inv1);
    }
}

// ---------------------------------------------------------------------------
// LayerNorm over rows of HDIM=1024; optional fp16 dual output.
// ---------------------------------------------------------------------------
__global__ __launch_bounds__(256)
void ln_kernel(const float* __restrict__ x, const float* __restrict__ gamma,
               const float* __restrict__ beta, float* __restrict__ y,
               __half* __restrict__ yh)
{
    const int row = blockIdx.x;
    const int t = threadIdx.x;
    const float* xr = x + (size_t)row * HDIM;

    float4 v = *(const float4*)(xr + t * 4);
    float s  = v.x + v.y + v.z + v.w;
    float s2 = v.x * v.x + v.y * v.y + v.z * v.z + v.w * v.w;

    #pragma unroll
    for (int o = 16; o > 0; o >>= 1) {
        s  += __shfl_xor_sync(0xffffffffu, s, o);
        s2 += __shfl_xor_sync(0xffffffffu, s2, o);
    }
    __shared__ float ws[8], ws2[8];
    const int w = t >> 5, lane = t & 31;
    if (lane == 0) { ws[w] = s; ws2[w] = s2; }
    __syncthreads();

    float ts = 0.0f, ts2 = 0.0f;
    #pragma unroll
    for (int i = 0; i < 8; i++) { ts += ws[i]; ts2 += ws2[i]; }

    const float mean = ts * (1.0f / HDIM);
    const float var  = ts2 * (1.0f / HDIM) - mean * mean;
    const float rstd = rsqrtf(var + 1e-12f);

    float4 g  = *(const float4*)(gamma + t * 4);
    float4 bb = *(const float4*)(beta  + t * 4);
    float4 o;
    o.x = (v.x - mean) * rstd * g.x + bb.x;
    o.y = (v.y - mean) * rstd * g.y + bb.y;
    o.z = (v.z - mean) * rstd * g.z + bb.z;
    o.w = (v.w - mean) * rstd * g.w + bb.w;
    *(float4*)(y + (size_t)row * HDIM + t * 4) = o;
    if (yh) {
        union { __half2 h2[2]; uint2 u; } p;
        p.h2[0] = __floats2half2_rn(o.x, o.y);
        p.h2[1] = __floats2half2_rn(o.z, o.w);
        ((uint2*)(yh + (size_t)row * HDIM))[t] = p.u;
    }
}

// ---------------------------------------------------------------------------
// Orchestration
// ---------------------------------------------------------------------------
extern "C" void kernel_launch(void* const* d_in, const int* in_sizes, int n_in,
                              void* d_out, int out_size)
{
    (void)in_sizes; (void)n_in; (void)out_size;

    const float* inp    = (const float*)d_in[0];
    const int*   mask   = (const int*)  d_in[1];
    const float* Wq     = (const float*)d_in[2];
    const float* bq     = (const float*)d_in[3];
    const float* Wk     = (const float*)d_in[4];
    const float* bk     = (const float*)d_in[5];
    const float* Wv     = (const float*)d_in[6];
    const float* bv     = (const float*)d_in[7];
    const float* Wao    = (const float*)d_in[8];
    const float* bao    = (const float*)d_in[9];
    const float* gamma1 = (const float*)d_in[10];
    const float* beta1  = (const float*)d_in[11];
    const float* Wi     = (const float*)d_in[12];
    const float* bi     = (const float*)d_in[13];
    const float* Wo     = (const float*)d_in[14];
    const float* bo     = (const float*)d_in[15];
    const float* gamma2 = (const float*)d_in[16];
    const float* beta2  = (const float*)d_in[17];
    float* out = (float*)d_out;

    float *t1, *attn;
    cudaGetSymbolAddress((void**)&t1,   g_t1);
    cudaGetSymbolAddress((void**)&attn, g_attn);

    __half *xh, *qh, *kh, *vh, *ctx, *attnh, *inter, *adder;
    __half *wqkv, *wao, *wi, *wo;
    cudaGetSymbolAddress((void**)&xh,    g_xh);
    cudaGetSymbolAddress((void**)&qh,    g_qh);
    cudaGetSymbolAddress((void**)&kh,    g_kh);
    cudaGetSymbolAddress((void**)&vh,    g_vh);
    cudaGetSymbolAddress((void**)&ctx,   g_ctx);
    cudaGetSymbolAddress((void**)&attnh, g_attnh);
    cudaGetSymbolAddress((void**)&inter, g_inter);
    cudaGetSymbolAddress((void**)&adder, g_adder);
    cudaGetSymbolAddress((void**)&wqkv, g_wqkv);
    cudaGetSymbolAddress((void**)&wao,  g_wao);
    cudaGetSymbolAddress((void**)&wi,   g_wi);
    cudaGetSymbolAddress((void**)&wo,   g_wo);

    cudaFuncSetAttribute(mma_gemm<0>, cudaFuncAttributeMaxDynamicSharedMemorySize, GEMM_SMEM);
    cudaFuncSetAttribute(mma_gemm<1>, cudaFuncAttributeMaxDynamicSharedMemorySize, GEMM_SMEM);
    cudaFuncSetAttribute(attn_kernel, cudaFuncAttributeMaxDynamicSharedMemorySize, ATTN_SMEM);

    dim3 blk256(256), blk128(128);
    const int nH4 = MROWS * HDIM / 4;
    const int nM4 = BATCH * SEQ * SEQ / 4;

    dim3 gQKV(3 * HDIM / 128, MROWS / 128);   // 24 x 32
    dim3 gH(HDIM / 128, MROWS / 128);         // 8 x 32
    dim3 gF(FFDIM / 128, MROWS / 128);        // 32 x 32

    // transpose grids: (N_out/64, K/64) where T is [N_out, K]
    cvt_kernel<<<(nH4 + 255) / 256, blk256>>>(inp, xh, nH4);
    mask_cvt_kernel<<<(nM4 + 255) / 256, blk256>>>(mask, adder, nM4);
    transpose_cvt_kernel<<<dim3(HDIM/64, HDIM/64), blk256>>>(Wq, wqkv, HDIM, HDIM);
    transpose_cvt_kernel<<<dim3(HDIM/64, HDIM/64), blk256>>>(Wk, wqkv + (size_t)HDIM*HDIM, HDIM, HDIM);
    transpose_cvt_kernel<<<dim3(HDIM/64, HDIM/64), blk256>>>(Wv, wqkv + (size_t)2*HDIM*HDIM, HDIM, HDIM);

    // fused QKV projection
    mma_gemm<1><<<gQKV, blk128, GEMM_SMEM>>>(xh, wqkv, bq, bk, bv, nullptr,
                                             nullptr, qh, kh, vh,
                                             MROWS, 3 * HDIM, HDIM, 0, 1.0f);

    transpose_cvt_kernel<<<dim3(HDIM/64, HDIM/64), blk256>>>(Wao, wao, HDIM, HDIM);
    transpose_cvt_kernel<<<dim3(FFDIM/64, HDIM/64), blk256>>>(Wi, wi, HDIM, FFDIM);
    transpose_cvt_kernel<<<dim3(HDIM/64, FFDIM/64), blk256>>>(Wo, wo, FFDIM, HDIM);

    // tensor-core flash attention -> fp16 ctx
    attn_kernel<<<dim3(SEQ / 64, NHEAD, BATCH), blk128, ATTN_SMEM>>>(qh, kh, vh, adder, ctx);

    // AO projection + residual, LN1
    mma_gemm<0><<<gH, blk128, GEMM_SMEM>>>(ctx, wao, bao, nullptr, nullptr, inp,
                                           t1, nullptr, nullptr, nullptr,
                                           MROWS, HDIM, HDIM, 0, 1.0f);
    ln_kernel<<<MROWS, blk256>>>(t1, gamma1, beta1, attn, attnh);

    // FFN
    mma_gemm<0><<<gF, blk128, GEMM_SMEM>>>(attnh, wi, bi, nullptr, nullptr, nullptr,
                                           nullptr, inter, nullptr, nullptr,
                                           MROWS, FFDIM, HDIM, 1, 1.0f);
    mma_gemm<0><<<gH, blk128, GEMM_SMEM>>>(inter, wo, bo, nullptr, nullptr, attn,
                                           t1, nullptr, nullptr, nullptr,
                                           MROWS, HDIM, FFDIM, 0, 1.0f);
    ln_kernel<<<MROWS, blk256>>>(t1, gamma2, beta2, out, nullptr);
}

// round 12
// speedup vs baseline: 1.3219x; 1.0255x over previous
#include <cuda_runtime.h>
#include <cuda_fp16.h>
#include <math.h>
#include <stdint.h>

#define BATCH 8
#define SEQ   512
#define HDIM  1024
#define FFDIM 4096
#define NHEAD 16
#define DHEAD 64
#define MROWS (BATCH*SEQ)   // 4096

// ---------------------------------------------------------------------------
// Static device scratch
// ---------------------------------------------------------------------------
__device__ float g_t1[(size_t)MROWS * HDIM];
__device__ float g_attn[(size_t)MROWS * HDIM];

__device__ __half g_xh[(size_t)MROWS * HDIM];
__device__ __half g_qh[(size_t)MROWS * HDIM];       // Q (prescaled 0.125)
__device__ __half g_kh[(size_t)MROWS * HDIM];
__device__ __half g_vh[(size_t)MROWS * HDIM];
__device__ __half g_ctx[(size_t)MROWS * HDIM];
__device__ __half g_attnh[(size_t)MROWS * HDIM];
__device__ __half g_inter[(size_t)MROWS * FFDIM];
__device__ __half g_adder[(size_t)BATCH * SEQ * SEQ];

__device__ __half g_wqkv[(size_t)3 * HDIM * HDIM];  // packed, transposed [N,K]
__device__ __half g_wao[(size_t)HDIM * HDIM];
__device__ __half g_wi[(size_t)FFDIM * HDIM];
__device__ __half g_wo[(size_t)HDIM * FFDIM];

__device__ __forceinline__ float gelu_tanh(float x) {
    float x3 = x * x * x;
    return 0.5f * x * (1.0f + tanhf(0.7978845608028654f * (x + 0.044715f * x3)));
}
__device__ __forceinline__ uint32_t h2_as_u32(__half2 h) {
    union { __half2 h2; uint32_t u; } c; c.h2 = h; return c.u;
}

// ---------------------------------------------------------------------------
// PTX helpers
// ---------------------------------------------------------------------------
__device__ __forceinline__ uint32_t smem_u32(const void* p) {
    uint32_t a;
    asm("{ .reg .u64 t; cvta.to.shared.u64 t, %1; cvt.u32.u64 %0, t; }"
        : "=r"(a) : "l"(p));
    return a;
}
__device__ __forceinline__ void cp16(uint32_t saddr, const void* gaddr) {
    asm volatile("cp.async.cg.shared.global [%0], [%1], 16;" :: "r"(saddr), "l"(gaddr));
}
#define CP_COMMIT() asm volatile("cp.async.commit_group;" ::: "memory")
#define CP_WAIT(n)  asm volatile("cp.async.wait_group %0;" :: "n"(n) : "memory")

__device__ __forceinline__ void ldm_x4(uint32_t* r, uint32_t addr) {
    asm volatile("ldmatrix.sync.aligned.m8n8.x4.shared.b16 {%0,%1,%2,%3}, [%4];"
        : "=r"(r[0]), "=r"(r[1]), "=r"(r[2]), "=r"(r[3]) : "r"(addr));
}
__device__ __forceinline__ void ldm_x4_t(uint32_t* r, uint32_t addr) {
    asm volatile("ldmatrix.sync.aligned.m8n8.x4.trans.shared.b16 {%0,%1,%2,%3}, [%4];"
        : "=r"(r[0]), "=r"(r[1]), "=r"(r[2]), "=r"(r[3]) : "r"(addr));
}
__device__ __forceinline__ void mma_f16(float* c, const uint32_t* a, const uint32_t* b) {
    asm volatile(
        "mma.sync.aligned.m16n8k16.row.col.f32.f16.f16.f32 "
        "{%0,%1,%2,%3}, {%4,%5,%6,%7}, {%8,%9}, {%0,%1,%2,%3};"
        : "+f"(c[0]), "+f"(c[1]), "+f"(c[2]), "+f"(c[3])
        : "r"(a[0]), "r"(a[1]), "r"(a[2]), "r"(a[3]), "r"(b[0]), "r"(b[1]));
}

// ---------------------------------------------------------------------------
// Unified prep kernel: ONE launch does input cvt, mask cvt, and all 6 weight
// transposes (block-range dispatch). All prep memory ops overlap.
// Block ranges (256 threads each):
//   [0,4096)        cvt inp -> xh            (nH4 = 1048576 float4)
//   [4096,6144)     mask -> adder            (nM4 = 524288 int4)
//   [6144,7168)     Wq  -> wqkv[0]      (32x32-tile transpose, 1024 blocks)
//   [7168,8192)     Wk  -> wqkv[1M]
//   [8192,9216)     Wv  -> wqkv[2M]
//   [9216,10240)    Wao -> wao
//   [10240,14336)   Wi  -> wi  (4096 blocks)
//   [14336,18432)   Wo  -> wo  (4096 blocks)
// ---------------------------------------------------------------------------
#define PREP_BLOCKS 18432

__global__ __launch_bounds__(256)
void prep_kernel(const float* __restrict__ inp, const int* __restrict__ mask,
                 const float* __restrict__ Wq, const float* __restrict__ Wk,
                 const float* __restrict__ Wv, const float* __restrict__ Wao,
                 const float* __restrict__ Wi, const float* __restrict__ Wo,
                 __half* __restrict__ xh, __half* __restrict__ adder,
                 __half* __restrict__ wqkv, __half* __restrict__ wao,
                 __half* __restrict__ wi, __half* __restrict__ wo)
{
    __shared__ float tile[32][33];
    const int bid = blockIdx.x;
    const int t = threadIdx.x;

    if (bid < 4096) {
        int i = bid * 256 + t;
        float4 v = ((const float4*)inp)[i];
        union { __half2 h2[2]; uint2 u; } p;
        p.h2[0] = __floats2half2_rn(v.x, v.y);
        p.h2[1] = __floats2half2_rn(v.z, v.w);
        ((uint2*)xh)[i] = p.u;
        return;
    }
    if (bid < 6144) {
        int i = (bid - 4096) * 256 + t;
        int4 v = ((const int4*)mask)[i];
        union { __half2 h2[2]; uint2 u; } p;
        p.h2[0] = __floats2half2_rn((1.0f - (float)v.x) * -10000.0f,
                                    (1.0f - (float)v.y) * -10000.0f);
        p.h2[1] = __floats2half2_rn((1.0f - (float)v.z) * -10000.0f,
                                    (1.0f - (float)v.w) * -10000.0f);
        ((uint2*)adder)[i] = p.u;
        return;
    }

    // transpose dispatch: W[K,N] fp32 -> T[N,K] fp16
    const float* W;
    __half* T;
    int K, N, lb;
    if (bid < 7168)       { W = Wq;  T = wqkv;                          K = HDIM;  N = HDIM;  lb = bid - 6144; }
    else if (bid < 8192)  { W = Wk;  T = wqkv + (size_t)HDIM * HDIM;    K = HDIM;  N = HDIM;  lb = bid - 7168; }
    else if (bid < 9216)  { W = Wv;  T = wqkv + (size_t)2 * HDIM * HDIM;K = HDIM;  N = HDIM;  lb = bid - 8192; }
    else if (bid < 10240) { W = Wao; T = wao;                           K = HDIM;  N = HDIM;  lb = bid - 9216; }
    else if (bid < 14336) { W = Wi;  T = wi;                            K = HDIM;  N = FFDIM; lb = bid - 10240; }
    else                  { W = Wo;  T = wo;                            K = FFDIM; N = HDIM;  lb = bid - 14336; }

    const int nbx = N / 32;
    const int bx = lb % nbx;
    const int by = lb / nbx;
    const int tx = t & 31;
    const int ty = t >> 5;           // 0..7

    const int x = bx * 32 + tx;      // n
    const int y0 = by * 32;          // k base
    #pragma unroll
    for (int j = 0; j < 32; j += 8)
        tile[ty + j][tx] = W[(size_t)(y0 + ty + j) * N + x];
    __syncthreads();

    const int k = y0 + tx;
    #pragma unroll
    for (int j = 0; j < 32; j += 8) {
        int n = bx * 32 + ty + j;
        T[(size_t)n * K + k] = __float2half_rn(tile[tx][ty + j]);
    }
}

// ---------------------------------------------------------------------------
// fp16 GEMM via mma.sync (R8 config, proven 422us). CTA 128x128, 4 warps
// (2x2), warp tile 64x64. KC=64, 3-stage cp.async, XOR-swizzled 128B rows,
// register double-buffered fragments. launch_bounds(128,2) -> 2 CTA/SM.
// MODE 0: C = A@B^T + bias (*oscale) (+res) (gelu) -> Cf (fp32) or Ch (fp16)
// MODE 1: fused QKV: N=3072 packed; per-1024 segment bias/out/scale.
// ---------------------------------------------------------------------------
#define KC 64
#define TILE_B 16384                     // 128 rows x 128 B
#define STAGE_B (2 * TILE_B)             // 32768
#define GEMM_SMEM (3 * STAGE_B)          // 98304

#define SWZ(r, c) ((uint32_t)(r) * 128 + ((uint32_t)((c) ^ ((r) & 7)) * 16))

template<int MODE>
__global__ __launch_bounds__(128, 2)
void mma_gemm(const __half* __restrict__ A, const __half* __restrict__ Bm,
              const float* __restrict__ bias, const float* __restrict__ bias2,
              const float* __restrict__ bias3, const float* __restrict__ res,
              float* __restrict__ Cf, __half* __restrict__ Ch,
              __half* __restrict__ Ch2, __half* __restrict__ Ch3,
              int M, int N, int K, int do_gelu, float oscale)
{
    extern __shared__ char sm[];
    const uint32_t sbase = smem_u32(sm);

    const int t    = threadIdx.x;
    const int lane = t & 31;
    const int w    = t >> 5;          // 0..3
    const int wm   = w & 1;           // 2 row groups (64)
    const int wn   = w >> 1;          // 2 col groups (64)
    const int row0 = blockIdx.y * 128;
    const int col0 = blockIdx.x * 128;

    const int NC = K / KC;

    const int l_r = t >> 3;
    const int l_c = t & 7;

    const int a_r  = wm * 64 + (lane & 15);
    const int a_ch = lane >> 4;
    const int b_r  = wn * 64 + (lane >> 4) * 8 + (lane & 7);   // + p*16
    const int b_ch = (lane >> 3) & 1;

    float acc[4][8][4];
    #pragma unroll
    for (int i = 0; i < 4; i++)
        #pragma unroll
        for (int j = 0; j < 8; j++)
            #pragma unroll
            for (int e = 0; e < 4; e++) acc[i][j][e] = 0.0f;

    #pragma unroll
    for (int pc = 0; pc < 2; pc++) {
        const int kofs = pc * KC;
        const uint32_t bb = sbase + pc * STAGE_B;
        #pragma unroll
        for (int j = 0; j < 8; j++) {
            int r = l_r + j * 16;
            uint32_t sw = SWZ(r, l_c);
            cp16(bb + sw,          A  + (size_t)(row0 + r) * K + kofs + l_c * 8);
            cp16(bb + TILE_B + sw, Bm + (size_t)(col0 + r) * K + kofs + l_c * 8);
        }
        CP_COMMIT();
    }

    uint32_t af[2][4][4];
    uint32_t bf[2][16];

    for (int i = 0; i < NC; i++) {
        CP_WAIT(1);
        __syncthreads();

        if (i + 2 < NC) {
            const int kofs = (i + 2) * KC;
            const uint32_t bb = sbase + ((i + 2) % 3) * STAGE_B;
            #pragma unroll
            for (int j = 0; j < 8; j++) {
                int r = l_r + j * 16;
                uint32_t sw = SWZ(r, l_c);
                cp16(bb + sw,          A  + (size_t)(row0 + r) * K + kofs + l_c * 8);
                cp16(bb + TILE_B + sw, Bm + (size_t)(col0 + r) * K + kofs + l_c * 8);
            }
        }
        CP_COMMIT();

        const uint32_t baseA = sbase + (i % 3) * STAGE_B;
        const uint32_t baseB = baseA + TILE_B;

        #pragma unroll
        for (int p = 0; p < 4; p++)
            ldm_x4(&bf[0][p * 4], baseB + SWZ(b_r + p * 16, b_ch));
        #pragma unroll
        for (int mt = 0; mt < 4; mt++)
            ldm_x4(af[0][mt], baseA + SWZ(a_r + mt * 16, a_ch));

        #pragma unroll
        for (int ks = 0; ks < 4; ks++) {
            const int cur = ks & 1, nxt = cur ^ 1;
            if (ks < 3) {
                #pragma unroll
                for (int p = 0; p < 4; p++)
                    ldm_x4(&bf[nxt][p * 4],
                           baseB + SWZ(b_r + p * 16, (ks + 1) * 2 + b_ch));
                #pragma unroll
                for (int mt = 0; mt < 4; mt++)
                    ldm_x4(af[nxt][mt],
                           baseA + SWZ(a_r + mt * 16, (ks + 1) * 2 + a_ch));
            }
            #pragma unroll
            for (int mt = 0; mt < 4; mt++)
                #pragma unroll
                for (int nt = 0; nt < 8; nt++)
                    mma_f16(acc[mt][nt], af[cur][mt], &bf[cur][nt * 2]);
        }
    }

    const int qr = lane >> 2;
    const int qc = (lane & 3) * 2;

    if (MODE == 1) {
        const int seg = col0 >> 10;                       // 0=Q, 1=K, 2=V
        const float* bseg = (seg == 0) ? bias : (seg == 1) ? bias2 : bias3;
        __half* outp      = (seg == 0) ? Ch   : (seg == 1) ? Ch2   : Ch3;
        const float osc   = (seg == 0) ? 0.125f : 1.0f;
        #pragma unroll
        for (int mt = 0; mt < 4; mt++) {
            #pragma unroll
            for (int nt = 0; nt < 8; nt++) {
                const int gr0 = row0 + wm * 64 + mt * 16 + qr;
                const int gcl = (col0 & 1023) + wn * 64 + nt * 8 + qc;
                float2 bv = *(const float2*)(bseg + gcl);
                *(__half2*)(outp + (size_t)gr0 * HDIM + gcl) =
                    __floats2half2_rn((acc[mt][nt][0] + bv.x) * osc,
                                      (acc[mt][nt][1] + bv.y) * osc);
                *(__half2*)(outp + (size_t)(gr0 + 8) * HDIM + gcl) =
                    __floats2half2_rn((acc[mt][nt][2] + bv.x) * osc,
                                      (acc[mt][nt][3] + bv.y) * osc);
            }
        }
        return;
    }

    #pragma unroll
    for (int mt = 0; mt < 4; mt++) {
        #pragma unroll
        for (int nt = 0; nt < 8; nt++) {
            const int gr0 = row0 + wm * 64 + mt * 16 + qr;
            const int gc  = col0 + wn * 64 + nt * 8 + qc;
            float2 bv = *(const float2*)(bias + gc);
            float o0 = (acc[mt][nt][0] + bv.x) * oscale;
            float o1 = (acc[mt][nt][1] + bv.y) * oscale;
            float o2 = (acc[mt][nt][2] + bv.x) * oscale;
            float o3 = (acc[mt][nt][3] + bv.y) * oscale;
            if (res) {
                float2 r0v = *(const float2*)(res + (size_t)gr0 * N + gc);
                float2 r1v = *(const float2*)(res + (size_t)(gr0 + 8) * N + gc);
                o0 += r0v.x; o1 += r0v.y; o2 += r1v.x; o3 += r1v.y;
            }
            if (do_gelu) {
                o0 = gelu_tanh(o0); o1 = gelu_tanh(o1);
                o2 = gelu_tanh(o2); o3 = gelu_tanh(o3);
            }
            if (Cf) {
                *(float2*)(Cf + (size_t)gr0 * N + gc)       = make_float2(o0, o1);
                *(float2*)(Cf + (size_t)(gr0 + 8) * N + gc) = make_float2(o2, o3);
            } else {
                *(__half2*)(Ch + (size_t)gr0 * N + gc)       = __floats2half2_rn(o0, o1);
                *(__half2*)(Ch + (size_t)(gr0 + 8) * N + gc) = __floats2half2_rn(o2, o3);
            }
        }
    }
}

// ---------------------------------------------------------------------------
// Tensor-core flash attention (fp16 mma, fp32 softmax/accum). Unchanged.
// ---------------------------------------------------------------------------
#define ALDA 72
#define SQ_OFF   0
#define SK_OFF   9216
#define SV_OFF   36864
#define SAD_OFF  64512
#define ATTN_SMEM 89088

__global__ __launch_bounds__(128)
void attn_kernel(const __half* __restrict__ Qg, const __half* __restrict__ Kg,
                 const __half* __restrict__ Vg, const __half* __restrict__ ADg,
                 __half* __restrict__ O)
{
    extern __shared__ char sm[];
    const uint32_t sbase = smem_u32(sm);

    const int t = threadIdx.x;
    const int lane = t & 31;
    const int w = t >> 5;
    const int b = blockIdx.z, h = blockIdx.y;
    const int q0 = blockIdx.x * 64;

    const int qr = lane >> 2;
    const int qc = (lane & 3) * 2;

    const int lr = t >> 1;
    const int lc2 = (t & 1) * 4;

    auto issue = [&](int ic) {
        const int slot = ic % 3;
        const int kc = ic * 64;
        const __half* kg = Kg + (size_t)(b * SEQ + kc + lr) * HDIM + h * DHEAD;
        const __half* vg = Vg + (size_t)(b * SEQ + kc + lr) * HDIM + h * DHEAD;
        const __half* ag = ADg + (size_t)(b * SEQ + q0 + lr) * SEQ + kc;
        uint32_t ks = sbase + SK_OFF + slot * 9216 + lr * (ALDA * 2);
        uint32_t vs = sbase + SV_OFF + slot * 9216 + lr * (ALDA * 2);
        uint32_t as = sbase + SAD_OFF + slot * 8192 + lr * 128;
        #pragma unroll
        for (int c = 0; c < 4; c++) {
            cp16(ks + (lc2 + c) * 16, kg + (lc2 + c) * 8);
            cp16(vs + (lc2 + c) * 16, vg + (lc2 + c) * 8);
            cp16(as + (lc2 + c) * 16, ag + (lc2 + c) * 8);
        }
    };

    {
        const __half* qg = Qg + (size_t)(b * SEQ + q0 + lr) * HDIM + h * DHEAD;
        uint32_t qs = sbase + SQ_OFF + lr * (ALDA * 2);
        #pragma unroll
        for (int c = 0; c < 4; c++)
            cp16(qs + (lc2 + c) * 16, qg + (lc2 + c) * 8);
        issue(0);
        CP_COMMIT();
        issue(1);
        CP_COMMIT();
    }

    const int a_row = w * 16 + (lane & 15);
    const int a_col = (lane >> 4) * 8;
    const int b_nrow = (lane >> 4) * 8 + (lane & 7);
    const int b_kcol = ((lane >> 3) & 1) * 8;
    const int v_krow = lane & 15;
    const int v_ncol = (lane >> 4) * 8;

    uint32_t qf[4][4];
    float Oa[8][4];
    #pragma unroll
    for (int i = 0; i < 8; i++)
        #pragma unroll
        for (int e = 0; e < 4; e++) Oa[i][e] = 0.0f;
    float m0 = -1e30f, m1 = -1e30f, l0 = 0.0f, l1 = 0.0f;

    for (int ic = 0; ic < 8; ic++) {
        CP_WAIT(1);
        __syncthreads();

        if (ic == 0) {
            #pragma unroll
            for (int ks = 0; ks < 4; ks++) {
                uint32_t off = (uint32_t)a_row * (ALDA * 2) + (ks * 16 + a_col) * 2;
                ldm_x4(qf[ks], sbase + SQ_OFF + off);
            }
        }
        if (ic + 2 < 8) issue(ic + 2);
        CP_COMMIT();

        const int slot = ic % 3;
        const uint32_t baseK = sbase + SK_OFF + slot * 9216;
        const uint32_t baseV = sbase + SV_OFF + slot * 9216;
        const uint32_t baseAD = sbase + SAD_OFF + slot * 8192;

        float s[8][4];
        #pragma unroll
        for (int nt = 0; nt < 8; nt++) {
            uint32_t ad0 = (baseAD - sbase) + ((w * 16 + qr) * 64 + nt * 8 + qc) * 2;
            float2 f0 = __half22float2(*(const __half2*)(sm + ad0));
            float2 f1 = __half22float2(*(const __half2*)(sm + ad0 + 8 * 128));
            s[nt][0] = f0.x; s[nt][1] = f0.y;
            s[nt][2] = f1.x; s[nt][3] = f1.y;
        }
        #pragma unroll
        for (int nb = 0; nb < 4; nb++) {
            #pragma unroll
            for (int ks = 0; ks < 4; ks++) {
                uint32_t bfr[4];
                uint32_t off = (uint32_t)(nb * 16 + b_nrow) * (ALDA * 2)
                             + (ks * 16 + b_kcol) * 2;
                ldm_x4(bfr, baseK + off);
                mma_f16(s[2 * nb],     qf[ks], &bfr[0]);
                mma_f16(s[2 * nb + 1], qf[ks], &bfr[2]);
            }
        }

        float mx0 = -1e30f, mx1 = -1e30f;
        #pragma unroll
        for (int nt = 0; nt < 8; nt++) {
            mx0 = fmaxf(mx0, fmaxf(s[nt][0], s[nt][1]));
            mx1 = fmaxf(mx1, fmaxf(s[nt][2], s[nt][3]));
        }
        mx0 = fmaxf(mx0, __shfl_xor_sync(0xffffffffu, mx0, 1));
        mx0 = fmaxf(mx0, __shfl_xor_sync(0xffffffffu, mx0, 2));
        mx1 = fmaxf(mx1, __shfl_xor_sync(0xffffffffu, mx1, 1));
        mx1 = fmaxf(mx1, __shfl_xor_sync(0xffffffffu, mx1, 2));

        const float m0n = fmaxf(m0, mx0);
        const float m1n = fmaxf(m1, mx1);
        const float al0 = __expf(m0 - m0n);
        const float al1 = __expf(m1 - m1n);

        float sum0 = 0.0f, sum1 = 0.0f;
        uint32_t ph[4][4];
        #pragma unroll
        for (int j = 0; j < 4; j++) {
            float p00 = __expf(s[2 * j][0] - m0n);
            float p01 = __expf(s[2 * j][1] - m0n);
            float p02 = __expf(s[2 * j][2] - m1n);
            float p03 = __expf(s[2 * j][3] - m1n);
            float p10 = __expf(s[2 * j + 1][0] - m0n);
            float p11 = __expf(s[2 * j + 1][1] - m0n);
            float p12 = __expf(s[2 * j + 1][2] - m1n);
            float p13 = __expf(s[2 * j + 1][3] - m1n);
            sum0 += p00 + p01 + p10 + p11;
            sum1 += p02 + p03 + p12 + p13;
            ph[j][0] = h2_as_u32(__floats2half2_rn(p00, p01));
            ph[j][1] = h2_as_u32(__floats2half2_rn(p02, p03));
            ph[j][2] = h2_as_u32(__floats2half2_rn(p10, p11));
            ph[j][3] = h2_as_u32(__floats2half2_rn(p12, p13));
        }
        sum0 += __shfl_xor_sync(0xffffffffu, sum0, 1);
        sum0 += __shfl_xor_sync(0xffffffffu, sum0, 2);
        sum1 += __shfl_xor_sync(0xffffffffu, sum1, 1);
        sum1 += __shfl_xor_sync(0xffffffffu, sum1, 2);

        l0 = l0 * al0 + sum0;
        l1 = l1 * al1 + sum1;
        m0 = m0n; m1 = m1n;

        #pragma unroll
        for (int nt = 0; nt < 8; nt++) {
            Oa[nt][0] *= al0; Oa[nt][1] *= al0;
            Oa[nt][2] *= al1; Oa[nt][3] *= al1;
        }

        #pragma unroll
        for (int j = 0; j < 4; j++) {
            #pragma unroll
            for (int nt2 = 0; nt2 < 4; nt2++) {
                uint32_t vf[4];
                uint32_t off = (uint32_t)(j * 16 + v_krow) * (ALDA * 2)
                             + (nt2 * 16 + v_ncol) * 2;
                ldm_x4_t(vf, baseV + off);
                mma_f16(Oa[2 * nt2],     ph[j], &vf[0]);
                mma_f16(Oa[2 * nt2 + 1], ph[j], &vf[2]);
            }
        }
        __syncthreads();
    }

    const float inv0 = 1.0f / l0;
    const float inv1 = 1.0f / l1;
    const int gr0 = b * SEQ + q0 + w * 16 + qr;
    #pragma unroll
    for (int nt = 0; nt < 8; nt++) {
        const int gc = h * DHEAD + nt * 8 + qc;
        *(__half2*)(O + (size_t)gr0 * HDIM + gc) =
            __floats2half2_rn(Oa[nt][0] * inv0, Oa[nt][1] * inv0);
        *(__half2*)(O + (size_t)(gr0 + 8) * HDIM + gc) =
            __floats2half2_rn(Oa[nt][2] * inv1, Oa[nt][3] * inv1);
    }
}

// ---------------------------------------------------------------------------
// LayerNorm over rows of HDIM=1024; optional fp16 dual output.
// ---------------------------------------------------------------------------
__global__ __launch_bounds__(256)
void ln_kernel(const float* __restrict__ x, const float* __restrict__ gamma,
               const float* __restrict__ beta, float* __restrict__ y,
               __half* __restrict__ yh)
{
    const int row = blockIdx.x;
    const int t = threadIdx.x;
    const float* xr = x + (size_t)row * HDIM;

    float4 v = *(const float4*)(xr + t * 4);
    float s  = v.x + v.y + v.z + v.w;
    float s2 = v.x * v.x + v.y * v.y + v.z * v.z + v.w * v.w;

    #pragma unroll
    for (int o = 16; o > 0; o >>= 1) {
        s  += __shfl_xor_sync(0xffffffffu, s, o);
        s2 += __shfl_xor_sync(0xffffffffu, s2, o);
    }
    __shared__ float ws[8], ws2[8];
    const int w = t >> 5, lane = t & 31;
    if (lane == 0) { ws[w] = s; ws2[w] = s2; }
    __syncthreads();

    float ts = 0.0f, ts2 = 0.0f;
    #pragma unroll
    for (int i = 0; i < 8; i++) { ts += ws[i]; ts2 += ws2[i]; }

    const float mean = ts * (1.0f / HDIM);
    const float var  = ts2 * (1.0f / HDIM) - mean * mean;
    const float rstd = rsqrtf(var + 1e-12f);

    float4 g  = *(const float4*)(gamma + t * 4);
    float4 bb = *(const float4*)(beta  + t * 4);
    float4 o;
    o.x = (v.x - mean) * rstd * g.x + bb.x;
    o.y = (v.y - mean) * rstd * g.y + bb.y;
    o.z = (v.z - mean) * rstd * g.z + bb.z;
    o.w = (v.w - mean) * rstd * g.w + bb.w;
    *(float4*)(y + (size_t)row * HDIM + t * 4) = o;
    if (yh) {
        union { __half2 h2[2]; uint2 u; } p;
        p.h2[0] = __floats2half2_rn(o.x, o.y);
        p.h2[1] = __floats2half2_rn(o.z, o.w);
        ((uint2*)(yh + (size_t)row * HDIM))[t] = p.u;
    }
}

// ---------------------------------------------------------------------------
// Orchestration
// ---------------------------------------------------------------------------
extern "C" void kernel_launch(void* const* d_in, const int* in_sizes, int n_in,
                              void* d_out, int out_size)
{
    (void)in_sizes; (void)n_in; (void)out_size;

    const float* inp    = (const float*)d_in[0];
    const int*   mask   = (const int*)  d_in[1];
    const float* Wq     = (const float*)d_in[2];
    const float* bq     = (const float*)d_in[3];
    const float* Wk     = (const float*)d_in[4];
    const float* bk     = (const float*)d_in[5];
    const float* Wv     = (const float*)d_in[6];
    const float* bv     = (const float*)d_in[7];
    const float* Wao    = (const float*)d_in[8];
    const float* bao    = (const float*)d_in[9];
    const float* gamma1 = (const float*)d_in[10];
    const float* beta1  = (const float*)d_in[11];
    const float* Wi     = (const float*)d_in[12];
    const float* bi     = (const float*)d_in[13];
    const float* Wo     = (const float*)d_in[14];
    const float* bo     = (const float*)d_in[15];
    const float* gamma2 = (const float*)d_in[16];
    const float* beta2  = (const float*)d_in[17];
    float* out = (float*)d_out;

    float *t1, *attn;
    cudaGetSymbolAddress((void**)&t1,   g_t1);
    cudaGetSymbolAddress((void**)&attn, g_attn);

    __half *xh, *qh, *kh, *vh, *ctx, *attnh, *inter, *adder;
    __half *wqkv, *wao, *wi, *wo;
    cudaGetSymbolAddress((void**)&xh,    g_xh);
    cudaGetSymbolAddress((void**)&qh,    g_qh);
    cudaGetSymbolAddress((void**)&kh,    g_kh);
    cudaGetSymbolAddress((void**)&vh,    g_vh);
    cudaGetSymbolAddress((void**)&ctx,   g_ctx);
    cudaGetSymbolAddress((void**)&attnh, g_attnh);
    cudaGetSymbolAddress((void**)&inter, g_inter);
    cudaGetSymbolAddress((void**)&adder, g_adder);
    cudaGetSymbolAddress((void**)&wqkv, g_wqkv);
    cudaGetSymbolAddress((void**)&wao,  g_wao);
    cudaGetSymbolAddress((void**)&wi,   g_wi);
    cudaGetSymbolAddress((void**)&wo,   g_wo);

    cudaFuncSetAttribute(mma_gemm<0>, cudaFuncAttributeMaxDynamicSharedMemorySize, GEMM_SMEM);
    cudaFuncSetAttribute(mma_gemm<1>, cudaFuncAttributeMaxDynamicSharedMemorySize, GEMM_SMEM);
    cudaFuncSetAttribute(attn_kernel, cudaFuncAttributeMaxDynamicSharedMemorySize, ATTN_SMEM);

    dim3 blk256(256), blk128(128);

    dim3 gQKV(3 * HDIM / 128, MROWS / 128);   // 24 x 32
    dim3 gH(HDIM / 128, MROWS / 128);         // 8 x 32
    dim3 gF(FFDIM / 128, MROWS / 128);        // 32 x 32

    // ONE prep launch: input cvt + mask cvt + all 6 weight transposes
    prep_kernel<<<PREP_BLOCKS, blk256>>>(inp, mask, Wq, Wk, Wv, Wao, Wi, Wo,
                                         xh, adder, wqkv, wao, wi, wo);

    // fused QKV projection
    mma_gemm<1><<<gQKV, blk128, GEMM_SMEM>>>(xh, wqkv, bq, bk, bv, nullptr,
                                             nullptr, qh, kh, vh,
                                             MROWS, 3 * HDIM, HDIM, 0, 1.0f);

    // tensor-core flash attention -> fp16 ctx
    attn_kernel<<<dim3(SEQ / 64, NHEAD, BATCH), blk128, ATTN_SMEM>>>(qh, kh, vh, adder, ctx);

    // AO projection + residual, LN1
    mma_gemm<0><<<gH, blk128, GEMM_SMEM>>>(ctx, wao, bao, nullptr, nullptr, inp,
                                           t1, nullptr, nullptr, nullptr,
                                           MROWS, HDIM, HDIM, 0, 1.0f);
    ln_kernel<<<MROWS, blk256>>>(t1, gamma1, beta1, attn, attnh);

    // FFN
    mma_gemm<0><<<gF, blk128, GEMM_SMEM>>>(attnh, wi, bi, nullptr, nullptr, nullptr,
                                           nullptr, inter, nullptr, nullptr,
                                           MROWS, FFDIM, HDIM, 1, 1.0f);
    mma_gemm<0><<<gH, blk128, GEMM_SMEM>>>(inter, wo, bo, nullptr, nullptr, attn,
                                           t1, nullptr, nullptr, nullptr,
                                           MROWS, HDIM, FFDIM, 0, 1.0f);
    ln_kernel<<<MROWS, blk256>>>(t1, gamma2, beta2, out, nullptr);
}

// round 13
// speedup vs baseline: 1.3471x; 1.0191x over previous
#include <cuda_runtime.h>
#include <cuda_fp16.h>
#include <math.h>
#include <stdint.h>

#define BATCH 8
#define SEQ   512
#define HDIM  1024
#define FFDIM 4096
#define NHEAD 16
#define DHEAD 64
#define MROWS (BATCH*SEQ)   // 4096

// ---------------------------------------------------------------------------
// Static device scratch
// ---------------------------------------------------------------------------
__device__ float g_t1[(size_t)MROWS * HDIM];
__device__ float g_attn[(size_t)MROWS * HDIM];

__device__ __half g_xh[(size_t)MROWS * HDIM];
__device__ __half g_qh[(size_t)MROWS * HDIM];       // Q (prescaled 0.125)
__device__ __half g_kh[(size_t)MROWS * HDIM];
__device__ __half g_vh[(size_t)MROWS * HDIM];
__device__ __half g_ctx[(size_t)MROWS * HDIM];
__device__ __half g_attnh[(size_t)MROWS * HDIM];
__device__ __half g_inter[(size_t)MROWS * FFDIM];
__device__ __half g_adder[(size_t)BATCH * SEQ * SEQ];

__device__ __half g_wqkv[(size_t)3 * HDIM * HDIM];  // packed, transposed [N,K]
__device__ __half g_wao[(size_t)HDIM * HDIM];
__device__ __half g_wi[(size_t)FFDIM * HDIM];
__device__ __half g_wo[(size_t)HDIM * FFDIM];

__device__ __forceinline__ float gelu_tanh(float x) {
    float x3 = x * x * x;
    return 0.5f * x * (1.0f + tanhf(0.7978845608028654f * (x + 0.044715f * x3)));
}
__device__ __forceinline__ uint32_t h2_as_u32(__half2 h) {
    union { __half2 h2; uint32_t u; } c; c.h2 = h; return c.u;
}

// ---------------------------------------------------------------------------
// PTX helpers
// ---------------------------------------------------------------------------
__device__ __forceinline__ uint32_t smem_u32(const void* p) {
    uint32_t a;
    asm("{ .reg .u64 t; cvta.to.shared.u64 t, %1; cvt.u32.u64 %0, t; }"
        : "=r"(a) : "l"(p));
    return a;
}
__device__ __forceinline__ void cp16(uint32_t saddr, const void* gaddr) {
    asm volatile("cp.async.cg.shared.global [%0], [%1], 16;" :: "r"(saddr), "l"(gaddr));
}
#define CP_COMMIT() asm volatile("cp.async.commit_group;" ::: "memory")
#define CP_WAIT(n)  asm volatile("cp.async.wait_group %0;" :: "n"(n) : "memory")

__device__ __forceinline__ void ldm_x4(uint32_t* r, uint32_t addr) {
    asm volatile("ldmatrix.sync.aligned.m8n8.x4.shared.b16 {%0,%1,%2,%3}, [%4];"
        : "=r"(r[0]), "=r"(r[1]), "=r"(r[2]), "=r"(r[3]) : "r"(addr));
}
__device__ __forceinline__ void ldm_x4_t(uint32_t* r, uint32_t addr) {
    asm volatile("ldmatrix.sync.aligned.m8n8.x4.trans.shared.b16 {%0,%1,%2,%3}, [%4];"
        : "=r"(r[0]), "=r"(r[1]), "=r"(r[2]), "=r"(r[3]) : "r"(addr));
}
__device__ __forceinline__ void mma_f16(float* c, const uint32_t* a, const uint32_t* b) {
    asm volatile(
        "mma.sync.aligned.m16n8k16.row.col.f32.f16.f16.f32 "
        "{%0,%1,%2,%3}, {%4,%5,%6,%7}, {%8,%9}, {%0,%1,%2,%3};"
        : "+f"(c[0]), "+f"(c[1]), "+f"(c[2]), "+f"(c[3])
        : "r"(a[0]), "r"(a[1]), "r"(a[2]), "r"(a[3]), "r"(b[0]), "r"(b[1]));
}

// ---------------------------------------------------------------------------
// Unified prep kernel (R12, proven): ONE launch does input cvt, mask cvt, and
// all 6 weight transposes via block-range dispatch.
// ---------------------------------------------------------------------------
#define PREP_BLOCKS 18432

__global__ __launch_bounds__(256)
void prep_kernel(const float* __restrict__ inp, const int* __restrict__ mask,
                 const float* __restrict__ Wq, const float* __restrict__ Wk,
                 const float* __restrict__ Wv, const float* __restrict__ Wao,
                 const float* __restrict__ Wi, const float* __restrict__ Wo,
                 __half* __restrict__ xh, __half* __restrict__ adder,
                 __half* __restrict__ wqkv, __half* __restrict__ wao,
                 __half* __restrict__ wi, __half* __restrict__ wo)
{
    __shared__ float tile[32][33];
    const int bid = blockIdx.x;
    const int t = threadIdx.x;

    if (bid < 4096) {
        int i = bid * 256 + t;
        float4 v = ((const float4*)inp)[i];
        union { __half2 h2[2]; uint2 u; } p;
        p.h2[0] = __floats2half2_rn(v.x, v.y);
        p.h2[1] = __floats2half2_rn(v.z, v.w);
        ((uint2*)xh)[i] = p.u;
        return;
    }
    if (bid < 6144) {
        int i = (bid - 4096) * 256 + t;
        int4 v = ((const int4*)mask)[i];
        union { __half2 h2[2]; uint2 u; } p;
        p.h2[0] = __floats2half2_rn((1.0f - (float)v.x) * -10000.0f,
                                    (1.0f - (float)v.y) * -10000.0f);
        p.h2[1] = __floats2half2_rn((1.0f - (float)v.z) * -10000.0f,
                                    (1.0f - (float)v.w) * -10000.0f);
        ((uint2*)adder)[i] = p.u;
        return;
    }

    const float* W;
    __half* T;
    int K, N, lb;
    if (bid < 7168)       { W = Wq;  T = wqkv;                          K = HDIM;  N = HDIM;  lb = bid - 6144; }
    else if (bid < 8192)  { W = Wk;  T = wqkv + (size_t)HDIM * HDIM;    K = HDIM;  N = HDIM;  lb = bid - 7168; }
    else if (bid < 9216)  { W = Wv;  T = wqkv + (size_t)2 * HDIM * HDIM;K = HDIM;  N = HDIM;  lb = bid - 8192; }
    else if (bid < 10240) { W = Wao; T = wao;                           K = HDIM;  N = HDIM;  lb = bid - 9216; }
    else if (bid < 14336) { W = Wi;  T = wi;                            K = HDIM;  N = FFDIM; lb = bid - 10240; }
    else                  { W = Wo;  T = wo;                            K = FFDIM; N = HDIM;  lb = bid - 14336; }

    const int nbx = N / 32;
    const int bx = lb % nbx;
    const int by = lb / nbx;
    const int tx = t & 31;
    const int ty = t >> 5;

    const int x = bx * 32 + tx;
    const int y0 = by * 32;
    #pragma unroll
    for (int j = 0; j < 32; j += 8)
        tile[ty + j][tx] = W[(size_t)(y0 + ty + j) * N + x];
    __syncthreads();

    const int k = y0 + tx;
    #pragma unroll
    for (int j = 0; j < 32; j += 8) {
        int n = bx * 32 + ty + j;
        T[(size_t)n * K + k] = __float2half_rn(tile[tx][ty + j]);
    }
}

// ---------------------------------------------------------------------------
// fp16 GEMM via mma.sync. CTA 128x128, 4 warps (2x2), warp tile 64x64.
// KC=64, 3-stage cp.async, XOR-swizzled 128B rows, register double-buffered
// fragments. NEW in R13: prefetch cp.async issuance is software-pipelined in
// 4 slices interleaved between ks-steps (removes front-of-chunk LSU burst).
// MODE 0: C = A@B^T + bias (*oscale) (+res) (gelu) -> Cf (fp32) or Ch (fp16)
// MODE 1: fused QKV: N=3072 packed; per-1024 segment bias/out/scale.
// ---------------------------------------------------------------------------
#define KC 64
#define TILE_B 16384                     // 128 rows x 128 B
#define STAGE_B (2 * TILE_B)             // 32768
#define GEMM_SMEM (3 * STAGE_B)          // 98304

#define SWZ(r, c) ((uint32_t)(r) * 128 + ((uint32_t)((c) ^ ((r) & 7)) * 16))

template<int MODE>
__global__ __launch_bounds__(128, 2)
void mma_gemm(const __half* __restrict__ A, const __half* __restrict__ Bm,
              const float* __restrict__ bias, const float* __restrict__ bias2,
              const float* __restrict__ bias3, const float* __restrict__ res,
              float* __restrict__ Cf, __half* __restrict__ Ch,
              __half* __restrict__ Ch2, __half* __restrict__ Ch3,
              int M, int N, int K, int do_gelu, float oscale)
{
    extern __shared__ char sm[];
    const uint32_t sbase = smem_u32(sm);

    const int t    = threadIdx.x;
    const int lane = t & 31;
    const int w    = t >> 5;          // 0..3
    const int wm   = w & 1;           // 2 row groups (64)
    const int wn   = w >> 1;          // 2 col groups (64)
    const int row0 = blockIdx.y * 128;
    const int col0 = blockIdx.x * 128;

    const int NC = K / KC;

    const int l_r = t >> 3;
    const int l_c = t & 7;

    const int a_r  = wm * 64 + (lane & 15);
    const int a_ch = lane >> 4;
    const int b_r  = wn * 64 + (lane >> 4) * 8 + (lane & 7);   // + p*16
    const int b_ch = (lane >> 3) & 1;

    float acc[4][8][4];
    #pragma unroll
    for (int i = 0; i < 4; i++)
        #pragma unroll
        for (int j = 0; j < 8; j++)
            #pragma unroll
            for (int e = 0; e < 4; e++) acc[i][j][e] = 0.0f;

    // prologue: chunks 0,1 (full-burst issue, once)
    #pragma unroll
    for (int pc = 0; pc < 2; pc++) {
        const int kofs = pc * KC;
        const uint32_t bb = sbase + pc * STAGE_B;
        #pragma unroll
        for (int j = 0; j < 8; j++) {
            int r = l_r + j * 16;
            uint32_t sw = SWZ(r, l_c);
            cp16(bb + sw,          A  + (size_t)(row0 + r) * K + kofs + l_c * 8);
            cp16(bb + TILE_B + sw, Bm + (size_t)(col0 + r) * K + kofs + l_c * 8);
        }
        CP_COMMIT();
    }

    uint32_t af[2][4][4];
    uint32_t bf[2][16];

    for (int i = 0; i < NC; i++) {
        CP_WAIT(1);
        __syncthreads();

        const uint32_t baseA = sbase + (i % 3) * STAGE_B;
        const uint32_t baseB = baseA + TILE_B;
        const bool do_pf = (i + 2 < NC);
        const int kofs = (i + 2) * KC;
        const uint32_t pb = sbase + ((i + 2) % 3) * STAGE_B;
        const __half* pA = A  + (size_t)(row0 + l_r) * K + kofs + l_c * 8;
        const __half* pB = Bm + (size_t)(col0 + l_r) * K + kofs + l_c * 8;

        // preload fragments for ks=0
        #pragma unroll
        for (int p = 0; p < 4; p++)
            ldm_x4(&bf[0][p * 4], baseB + SWZ(b_r + p * 16, b_ch));
        #pragma unroll
        for (int mt = 0; mt < 4; mt++)
            ldm_x4(af[0][mt], baseA + SWZ(a_r + mt * 16, a_ch));

        #pragma unroll
        for (int ks = 0; ks < 4; ks++) {
            const int cur = ks & 1, nxt = cur ^ 1;

            // prefetch slice ks for chunk i+2: 2 rows x (A,B) = 4 cp16
            if (do_pf) {
                #pragma unroll
                for (int jj = 0; jj < 2; jj++) {
                    int j = ks * 2 + jj;
                    int r = l_r + j * 16;
                    uint32_t sw = SWZ(r, l_c);
                    cp16(pb + sw,          pA + (size_t)(j * 16) * K);
                    cp16(pb + TILE_B + sw, pB + (size_t)(j * 16) * K);
                }
            }

            if (ks < 3) {
                #pragma unroll
                for (int p = 0; p < 4; p++)
                    ldm_x4(&bf[nxt][p * 4],
                           baseB + SWZ(b_r + p * 16, (ks + 1) * 2 + b_ch));
                #pragma unroll
                for (int mt = 0; mt < 4; mt++)
                    ldm_x4(af[nxt][mt],
                           baseA + SWZ(a_r + mt * 16, (ks + 1) * 2 + a_ch));
            }
            #pragma unroll
            for (int mt = 0; mt < 4; mt++)
                #pragma unroll
                for (int nt = 0; nt < 8; nt++)
                    mma_f16(acc[mt][nt], af[cur][mt], &bf[cur][nt * 2]);
        }
        CP_COMMIT();
    }

    const int qr = lane >> 2;
    const int qc = (lane & 3) * 2;

    if (MODE == 1) {
        const int seg = col0 >> 10;                       // 0=Q, 1=K, 2=V
        const float* bseg = (seg == 0) ? bias : (seg == 1) ? bias2 : bias3;
        __half* outp      = (seg == 0) ? Ch   : (seg == 1) ? Ch2   : Ch3;
        const float osc   = (seg == 0) ? 0.125f : 1.0f;
        #pragma unroll
        for (int mt = 0; mt < 4; mt++) {
            #pragma unroll
            for (int nt = 0; nt < 8; nt++) {
                const int gr0 = row0 + wm * 64 + mt * 16 + qr;
                const int gcl = (col0 & 1023) + wn * 64 + nt * 8 + qc;
                float2 bv = *(const float2*)(bseg + gcl);
                *(__half2*)(outp + (size_t)gr0 * HDIM + gcl) =
                    __floats2half2_rn((acc[mt][nt][0] + bv.x) * osc,
                                      (acc[mt][nt][1] + bv.y) * osc);
                *(__half2*)(outp + (size_t)(gr0 + 8) * HDIM + gcl) =
                    __floats2half2_rn((acc[mt][nt][2] + bv.x) * osc,
                                      (acc[mt][nt][3] + bv.y) * osc);
            }
        }
        return;
    }

    #pragma unroll
    for (int mt = 0; mt < 4; mt++) {
        #pragma unroll
        for (int nt = 0; nt < 8; nt++) {
            const int gr0 = row0 + wm * 64 + mt * 16 + qr;
            const int gc  = col0 + wn * 64 + nt * 8 + qc;
            float2 bv = *(const float2*)(bias + gc);
            float o0 = (acc[mt][nt][0] + bv.x) * oscale;
            float o1 = (acc[mt][nt][1] + bv.y) * oscale;
            float o2 = (acc[mt][nt][2] + bv.x) * oscale;
            float o3 = (acc[mt][nt][3] + bv.y) * oscale;
            if (res) {
                float2 r0v = *(const float2*)(res + (size_t)gr0 * N + gc);
                float2 r1v = *(const float2*)(res + (size_t)(gr0 + 8) * N + gc);
                o0 += r0v.x; o1 += r0v.y; o2 += r1v.x; o3 += r1v.y;
            }
            if (do_gelu) {
                o0 = gelu_tanh(o0); o1 = gelu_tanh(o1);
                o2 = gelu_tanh(o2); o3 = gelu_tanh(o3);
            }
            if (Cf) {
                *(float2*)(Cf + (size_t)gr0 * N + gc)       = make_float2(o0, o1);
                *(float2*)(Cf + (size_t)(gr0 + 8) * N + gc) = make_float2(o2, o3);
            } else {
                *(__half2*)(Ch + (size_t)gr0 * N + gc)       = __floats2half2_rn(o0, o1);
                *(__half2*)(Ch + (size_t)(gr0 + 8) * N + gc) = __floats2half2_rn(o2, o3);
            }
        }
    }
}

// ---------------------------------------------------------------------------
// Tensor-core flash attention (fp16 mma, fp32 softmax/accum). Unchanged.
// ---------------------------------------------------------------------------
#define ALDA 72
#define SQ_OFF   0
#define SK_OFF   9216
#define SV_OFF   36864
#define SAD_OFF  64512
#define ATTN_SMEM 89088

__global__ __launch_bounds__(128)
void attn_kernel(const __half* __restrict__ Qg, const __half* __restrict__ Kg,
                 const __half* __restrict__ Vg, const __half* __restrict__ ADg,
                 __half* __restrict__ O)
{
    extern __shared__ char sm[];
    const uint32_t sbase = smem_u32(sm);

    const int t = threadIdx.x;
    const int lane = t & 31;
    const int w = t >> 5;
    const int b = blockIdx.z, h = blockIdx.y;
    const int q0 = blockIdx.x * 64;

    const int qr = lane >> 2;
    const int qc = (lane & 3) * 2;

    const int lr = t >> 1;
    const int lc2 = (t & 1) * 4;

    auto issue = [&](int ic) {
        const int slot = ic % 3;
        const int kc = ic * 64;
        const __half* kg = Kg + (size_t)(b * SEQ + kc + lr) * HDIM + h * DHEAD;
        const __half* vg = Vg + (size_t)(b * SEQ + kc + lr) * HDIM + h * DHEAD;
        const __half* ag = ADg + (size_t)(b * SEQ + q0 + lr) * SEQ + kc;
        uint32_t ks = sbase + SK_OFF + slot * 9216 + lr * (ALDA * 2);
        uint32_t vs = sbase + SV_OFF + slot * 9216 + lr * (ALDA * 2);
        uint32_t as = sbase + SAD_OFF + slot * 8192 + lr * 128;
        #pragma unroll
        for (int c = 0; c < 4; c++) {
            cp16(ks + (lc2 + c) * 16, kg + (lc2 + c) * 8);
            cp16(vs + (lc2 + c) * 16, vg + (lc2 + c) * 8);
            cp16(as + (lc2 + c) * 16, ag + (lc2 + c) * 8);
        }
    };

    {
        const __half* qg = Qg + (size_t)(b * SEQ + q0 + lr) * HDIM + h * DHEAD;
        uint32_t qs = sbase + SQ_OFF + lr * (ALDA * 2);
        #pragma unroll
        for (int c = 0; c < 4; c++)
            cp16(qs + (lc2 + c) * 16, qg + (lc2 + c) * 8);
        issue(0);
        CP_COMMIT();
        issue(1);
        CP_COMMIT();
    }

    const int a_row = w * 16 + (lane & 15);
    const int a_col = (lane >> 4) * 8;
    const int b_nrow = (lane >> 4) * 8 + (lane & 7);
    const int b_kcol = ((lane >> 3) & 1) * 8;
    const int v_krow = lane & 15;
    const int v_ncol = (lane >> 4) * 8;

    uint32_t qf[4][4];
    float Oa[8][4];
    #pragma unroll
    for (int i = 0; i < 8; i++)
        #pragma unroll
        for (int e = 0; e < 4; e++) Oa[i][e] = 0.0f;
    float m0 = -1e30f, m1 = -1e30f, l0 = 0.0f, l1 = 0.0f;

    for (int ic = 0; ic < 8; ic++) {
        CP_WAIT(1);
        __syncthreads();

        if (ic == 0) {
            #pragma unroll
            for (int ks = 0; ks < 4; ks++) {
                uint32_t off = (uint32_t)a_row * (ALDA * 2) + (ks * 16 + a_col) * 2;
                ldm_x4(qf[ks], sbase + SQ_OFF + off);
            }
        }
        if (ic + 2 < 8) issue(ic + 2);
        CP_COMMIT();

        const int slot = ic % 3;
        const uint32_t baseK = sbase + SK_OFF + slot * 9216;
        const uint32_t baseV = sbase + SV_OFF + slot * 9216;
        const uint32_t baseAD = sbase + SAD_OFF + slot * 8192;

        float s[8][4];
        #pragma unroll
        for (int nt = 0; nt < 8; nt++) {
            uint32_t ad0 = (baseAD - sbase) + ((w * 16 + qr) * 64 + nt * 8 + qc) * 2;
            float2 f0 = __half22float2(*(const __half2*)(sm + ad0));
            float2 f1 = __half22float2(*(const __half2*)(sm + ad0 + 8 * 128));
            s[nt][0] = f0.x; s[nt][1] = f0.y;
            s[nt][2] = f1.x; s[nt][3] = f1.y;
        }
        #pragma unroll
        for (int nb = 0; nb < 4; nb++) {
            #pragma unroll
            for (int ks = 0; ks < 4; ks++) {
                uint32_t bfr[4];
                uint32_t off = (uint32_t)(nb * 16 + b_nrow) * (ALDA * 2)
                             + (ks * 16 + b_kcol) * 2;
                ldm_x4(bfr, baseK + off);
                mma_f16(s[2 * nb],     qf[ks], &bfr[0]);
                mma_f16(s[2 * nb + 1], qf[ks], &bfr[2]);
            }
        }

        float mx0 = -1e30f, mx1 = -1e30f;
        #pragma unroll
        for (int nt = 0; nt < 8; nt++) {
            mx0 = fmaxf(mx0, fmaxf(s[nt][0], s[nt][1]));
            mx1 = fmaxf(mx1, fmaxf(s[nt][2], s[nt][3]));
        }
        mx0 = fmaxf(mx0, __shfl_xor_sync(0xffffffffu, mx0, 1));
        mx0 = fmaxf(mx0, __shfl_xor_sync(0xffffffffu, mx0, 2));
        mx1 = fmaxf(mx1, __shfl_xor_sync(0xffffffffu, mx1, 1));
        mx1 = fmaxf(mx1, __shfl_xor_sync(0xffffffffu, mx1, 2));

        const float m0n = fmaxf(m0, mx0);
        const float m1n = fmaxf(m1, mx1);
        const float al0 = __expf(m0 - m0n);
        const float al1 = __expf(m1 - m1n);

        float sum0 = 0.0f, sum1 = 0.0f;
        uint32_t ph[4][4];
        #pragma unroll
        for (int j = 0; j < 4; j++) {
            float p00 = __expf(s[2 * j][0] - m0n);
            float p01 = __expf(s[2 * j][1] - m0n);
            float p02 = __expf(s[2 * j][2] - m1n);
            float p03 = __expf(s[2 * j][3] - m1n);
            float p10 = __expf(s[2 * j + 1][0] - m0n);
            float p11 = __expf(s[2 * j + 1][1] - m0n);
            float p12 = __expf(s[2 * j + 1][2] - m1n);
            float p13 = __expf(s[2 * j + 1][3] - m1n);
            sum0 += p00 + p01 + p10 + p11;
            sum1 += p02 + p03 + p12 + p13;
            ph[j][0] = h2_as_u32(__floats2half2_rn(p00, p01));
            ph[j][1] = h2_as_u32(__floats2half2_rn(p02, p03));
            ph[j][2] = h2_as_u32(__floats2half2_rn(p10, p11));
            ph[j][3] = h2_as_u32(__floats2half2_rn(p12, p13));
        }
        sum0 += __shfl_xor_sync(0xffffffffu, sum0, 1);
        sum0 += __shfl_xor_sync(0xffffffffu, sum0, 2);
        sum1 += __shfl_xor_sync(0xffffffffu, sum1, 1);
        sum1 += __shfl_xor_sync(0xffffffffu, sum1, 2);

        l0 = l0 * al0 + sum0;
        l1 = l1 * al1 + sum1;
        m0 = m0n; m1 = m1n;

        #pragma unroll
        for (int nt = 0; nt < 8; nt++) {
            Oa[nt][0] *= al0; Oa[nt][1] *= al0;
            Oa[nt][2] *= al1; Oa[nt][3] *= al1;
        }

        #pragma unroll
        for (int j = 0; j < 4; j++) {
            #pragma unroll
            for (int nt2 = 0; nt2 < 4; nt2++) {
                uint32_t vf[4];
                uint32_t off = (uint32_t)(j * 16 + v_krow) * (ALDA * 2)
                             + (nt2 * 16 + v_ncol) * 2;
                ldm_x4_t(vf, baseV + off);
                mma_f16(Oa[2 * nt2],     ph[j], &vf[0]);
                mma_f16(Oa[2 * nt2 + 1], ph[j], &vf[2]);
            }
        }
        __syncthreads();
    }

    const float inv0 = 1.0f / l0;
    const float inv1 = 1.0f / l1;
    const int gr0 = b * SEQ + q0 + w * 16 + qr;
    #pragma unroll
    for (int nt = 0; nt < 8; nt++) {
        const int gc = h * DHEAD + nt * 8 + qc;
        *(__half2*)(O + (size_t)gr0 * HDIM + gc) =
            __floats2half2_rn(Oa[nt][0] * inv0, Oa[nt][1] * inv0);
        *(__half2*)(O + (size_t)(gr0 + 8) * HDIM + gc) =
            __floats2half2_rn(Oa[nt][2] * inv1, Oa[nt][3] * inv1);
    }
}

// ---------------------------------------------------------------------------
// LayerNorm over rows of HDIM=1024; optional fp16 dual output.
// ---------------------------------------------------------------------------
__global__ __launch_bounds__(256)
void ln_kernel(const float* __restrict__ x, const float* __restrict__ gamma,
               const float* __restrict__ beta, float* __restrict__ y,
               __half* __restrict__ yh)
{
    const int row = blockIdx.x;
    const int t = threadIdx.x;
    const float* xr = x + (size_t)row * HDIM;

    float4 v = *(const float4*)(xr + t * 4);
    float s  = v.x + v.y + v.z + v.w;
    float s2 = v.x * v.x + v.y * v.y + v.z * v.z + v.w * v.w;

    #pragma unroll
    for (int o = 16; o > 0; o >>= 1) {
        s  += __shfl_xor_sync(0xffffffffu, s, o);
        s2 += __shfl_xor_sync(0xffffffffu, s2, o);
    }
    __shared__ float ws[8], ws2[8];
    const int w = t >> 5, lane = t & 31;
    if (lane == 0) { ws[w] = s; ws2[w] = s2; }
    __syncthreads();

    float ts = 0.0f, ts2 = 0.0f;
    #pragma unroll
    for (int i = 0; i < 8; i++) { ts += ws[i]; ts2 += ws2[i]; }

    const float mean = ts * (1.0f / HDIM);
    const float var  = ts2 * (1.0f / HDIM) - mean * mean;
    const float rstd = rsqrtf(var + 1e-12f);

    float4 g  = *(const float4*)(gamma + t * 4);
    float4 bb = *(const float4*)(beta  + t * 4);
    float4 o;
    o.x = (v.x - mean) * rstd * g.x + bb.x;
    o.y = (v.y - mean) * rstd * g.y + bb.y;
    o.z = (v.z - mean) * rstd * g.z + bb.z;
    o.w = (v.w - mean) * rstd * g.w + bb.w;
    *(float4*)(y + (size_t)row * HDIM + t * 4) = o;
    if (yh) {
        union { __half2 h2[2]; uint2 u; } p;
        p.h2[0] = __floats2half2_rn(o.x, o.y);
        p.h2[1] = __floats2half2_rn(o.z, o.w);
        ((uint2*)(yh + (size_t)row * HDIM))[t] = p.u;
    }
}

// ---------------------------------------------------------------------------
// Orchestration
// ---------------------------------------------------------------------------
extern "C" void kernel_launch(void* const* d_in, const int* in_sizes, int n_in,
                              void* d_out, int out_size)
{
    (void)in_sizes; (void)n_in; (void)out_size;

    const float* inp    = (const float*)d_in[0];
    const int*   mask   = (const int*)  d_in[1];
    const float* Wq     = (const float*)d_in[2];
    const float* bq     = (const float*)d_in[3];
    const float* Wk     = (const float*)d_in[4];
    const float* bk     = (const float*)d_in[5];
    const float* Wv     = (const float*)d_in[6];
    const float* bv     = (const float*)d_in[7];
    const float* Wao    = (const float*)d_in[8];
    const float* bao    = (const float*)d_in[9];
    const float* gamma1 = (const float*)d_in[10];
    const float* beta1  = (const float*)d_in[11];
    const float* Wi     = (const float*)d_in[12];
    const float* bi     = (const float*)d_in[13];
    const float* Wo     = (const float*)d_in[14];
    const float* bo     = (const float*)d_in[15];
    const float* gamma2 = (const float*)d_in[16];
    const float* beta2  = (const float*)d_in[17];
    float* out = (float*)d_out;

    float *t1, *attn;
    cudaGetSymbolAddress((void**)&t1,   g_t1);
    cudaGetSymbolAddress((void**)&attn, g_attn);

    __half *xh, *qh, *kh, *vh, *ctx, *attnh, *inter, *adder;
    __half *wqkv, *wao, *wi, *wo;
    cudaGetSymbolAddress((void**)&xh,    g_xh);
    cudaGetSymbolAddress((void**)&qh,    g_qh);
    cudaGetSymbolAddress((void**)&kh,    g_kh);
    cudaGetSymbolAddress((void**)&vh,    g_vh);
    cudaGetSymbolAddress((void**)&ctx,   g_ctx);
    cudaGetSymbolAddress((void**)&attnh, g_attnh);
    cudaGetSymbolAddress((void**)&inter, g_inter);
    cudaGetSymbolAddress((void**)&adder, g_adder);
    cudaGetSymbolAddress((void**)&wqkv, g_wqkv);
    cudaGetSymbolAddress((void**)&wao,  g_wao);
    cudaGetSymbolAddress((void**)&wi,   g_wi);
    cudaGetSymbolAddress((void**)&wo,   g_wo);

    cudaFuncSetAttribute(mma_gemm<0>, cudaFuncAttributeMaxDynamicSharedMemorySize, GEMM_SMEM);
    cudaFuncSetAttribute(mma_gemm<1>, cudaFuncAttributeMaxDynamicSharedMemorySize, GEMM_SMEM);
    cudaFuncSetAttribute(attn_kernel, cudaFuncAttributeMaxDynamicSharedMemorySize, ATTN_SMEM);

    dim3 blk256(256), blk128(128);

    dim3 gQKV(3 * HDIM / 128, MROWS / 128);   // 24 x 32
    dim3 gH(HDIM / 128, MROWS / 128);         // 8 x 32
    dim3 gF(FFDIM / 128, MROWS / 128);        // 32 x 32

    // ONE prep launch: input cvt + mask cvt + all 6 weight transposes
    prep_kernel<<<PREP_BLOCKS, blk256>>>(inp, mask, Wq, Wk, Wv, Wao, Wi, Wo,
                                         xh, adder, wqkv, wao, wi, wo);

    // fused QKV projection
    mma_gemm<1><<<gQKV, blk128, GEMM_SMEM>>>(xh, wqkv, bq, bk, bv, nullptr,
                                             nullptr, qh, kh, vh,
                                             MROWS, 3 * HDIM, HDIM, 0, 1.0f);

    // tensor-core flash attention -> fp16 ctx
    attn_kernel<<<dim3(SEQ / 64, NHEAD, BATCH), blk128, ATTN_SMEM>>>(qh, kh, vh, adder, ctx);

    // AO projection + residual, LN1
    mma_gemm<0><<<gH, blk128, GEMM_SMEM>>>(ctx, wao, bao, nullptr, nullptr, inp,
                                           t1, nullptr, nullptr, nullptr,
                                           MROWS, HDIM, HDIM, 0, 1.0f);
    ln_kernel<<<MROWS, blk256>>>(t1, gamma1, beta1, attn, attnh);

    // FFN
    mma_gemm<0><<<gF, blk128, GEMM_SMEM>>>(attnh, wi, bi, nullptr, nullptr, nullptr,
                                           nullptr, inter, nullptr, nullptr,
                                           MROWS, FFDIM, HDIM, 1, 1.0f);
    mma_gemm<0><<<gH, blk128, GEMM_SMEM>>>(inter, wo, bo, nullptr, nullptr, attn,
                                           t1, nullptr, nullptr, nullptr,
                                           MROWS, HDIM, FFDIM, 0, 1.0f);
    ln_kernel<<<MROWS, blk256>>>(t1, gamma2, beta2, out, nullptr);
}